// round 1
// baseline (speedup 1.0000x reference)
#include <cuda_runtime.h>
#include <cuda_bf16.h>
#include <cstdint>
#include <cstdio>

#define BATCH 8
#define NSEED 2048
#define KPTS  16384
#define DIM   768
#define CH    256
#define BNS   (BATCH*NSEED)              // 16384
#define NFS   (BATCH*CH*NSEED)           // 4194304

// -------------------- device scratch (no allocations allowed) --------------------
__device__ float g_bestd[4*BNS];
__device__ int   g_besti[4*BNS];
__device__ float g_loss;

__global__ void k_zero() { g_loss = 0.0f; }

// -------------------- kernel 1: split-K argmin (1-NN) --------------------
// Normalization by (same centroid, same positive scale) is argmin-invariant,
// so we search on raw coordinates: d = |s|^2 + |p|^2 - 2 s.p
__global__ __launch_bounds__(128) void k_argmin(
    const float* __restrict__ seed, const float* __restrict__ pts)
{
    __shared__ float4 tile[2048];   // {x,y,z,|p|^2}
    int gs = blockIdx.x * 128 + threadIdx.x;      // global seed index 0..16383
    int b  = gs >> 11;                            // /2048
    int kbase = blockIdx.y * 4096;                // split-K quarter
    const float* pb = pts + ((size_t)b * KPTS + kbase) * 3;

    float sx = seed[gs*3+0], sy = seed[gs*3+1], sz = seed[gs*3+2];
    float s2 = sx*sx + sy*sy + sz*sz;
    float mx = -2.0f*sx, my = -2.0f*sy, mz = -2.0f*sz;

    float bd = 1e30f;
    int   bi = kbase;

    for (int t0 = 0; t0 < 4096; t0 += 2048) {
        for (int p = threadIdx.x; p < 2048; p += 128) {
            float x = pb[(t0+p)*3+0];
            float y = pb[(t0+p)*3+1];
            float z = pb[(t0+p)*3+2];
            tile[p] = make_float4(x, y, z, x*x + y*y + z*z);
        }
        __syncthreads();
        #pragma unroll 8
        for (int p = 0; p < 2048; ++p) {
            float4 v = tile[p];
            float d = fmaf(mx, v.x, fmaf(my, v.y, fmaf(mz, v.z, v.w + s2)));
            if (d < bd) { bd = d; bi = kbase + t0 + p; }   // strict < : first index wins (matches argmin)
        }
        __syncthreads();
    }
    g_bestd[blockIdx.y * BNS + gs] = bd;
    g_besti[blockIdx.y * BNS + gs] = bi;
}

// -------------------- packed fp32x2 helpers (Blackwell FFMA2) --------------------
__device__ __forceinline__ unsigned long long pack2(float a, float b) {
    unsigned long long r;
    asm("mov.b64 %0, {%1, %2};" : "=l"(r) : "r"(__float_as_uint(a)), "r"(__float_as_uint(b)));
    return r;
}
__device__ __forceinline__ float2 unpack2(unsigned long long v) {
    unsigned int lo, hi;
    asm("mov.b64 {%0, %1}, %2;" : "=r"(lo), "=r"(hi) : "l"(v));
    return make_float2(__uint_as_float(lo), __uint_as_float(hi));
}
__device__ __forceinline__ unsigned long long fma2(unsigned long long a,
                                                   unsigned long long b,
                                                   unsigned long long c) {
    unsigned long long d;
    asm("fma.rn.f32x2 %0, %1, %2, %3;" : "=l"(d) : "l"(a), "l"(b), "l"(c));
    return d;
}

// -------------------- shared-memory layout for the fused kernel --------------------
#define SM_WSM   0          // 256*33  = 8448 floats (padded W staging, conflict-free)
#define SM_GS    8448       // 768*16  = 12288 floats (gathered features; reused as xs/hs)
#define SM_RED   20736      // 2*256   = 512 floats (LN partial reduction)
#define SM_MU    21248      // 16
#define SM_RS    21264      // 16
#define SM_IDX   21280      // 16 ints
#define SMEM_FLOATS 21296
#define SMEM_BYTES  (SMEM_FLOATS * 4)

// out[r][j] += sum_c W[r*ldw + c] * S[c*16 + j]  for a 256-row x 16-col tile.
// W staged in chunks of 32 cols into padded smem; S rows broadcast via LDS.128.
__device__ __forceinline__ void gemm16(const float* __restrict__ W, int ldw, int cdim,
                                       const float* S, float* Wsm,
                                       unsigned long long acc[8], int tid)
{
    for (int c0 = 0; c0 < cdim; c0 += 32) {
        #pragma unroll
        for (int i = tid; i < 256*32; i += 256) {
            int r = i >> 5, c = i & 31;
            Wsm[r*33 + c] = W[(size_t)r*ldw + c0 + c];
        }
        __syncthreads();
        #pragma unroll
        for (int c = 0; c < 32; ++c) {
            float w = Wsm[tid*33 + c];
            unsigned long long w2 = pack2(w, w);
            const float4* g4 = reinterpret_cast<const float4*>(S + (c0 + c)*16);
            #pragma unroll
            for (int q = 0; q < 4; ++q) {
                float4 g = g4[q];
                acc[2*q]   = fma2(w2, pack2(g.x, g.y), acc[2*q]);
                acc[2*q+1] = fma2(w2, pack2(g.z, g.w), acc[2*q+1]);
            }
        }
        __syncthreads();
    }
}

// -------------------- kernel 2: merge + gather + proj + LN + adapter + loss --------------------
__global__ __launch_bounds__(256, 2) void k_fused(
    const float* __restrict__ feat, const float* __restrict__ f_teacher,
    const float* __restrict__ W_proj, const float* __restrict__ b_proj,
    const float* __restrict__ W_a1,   const float* __restrict__ b_a1,
    const float* __restrict__ W_a2,   const float* __restrict__ b_a2,
    float* __restrict__ out, int out_size)
{
    extern __shared__ float sm[];
    float* Wsm   = sm + SM_WSM;
    float* Gs    = sm + SM_GS;
    float* xs    = Gs;              // 256*16, reuse after projection
    float* hs    = Gs + 4096;       // 256*16
    float* red_s = sm + SM_RED;
    float* red_q = sm + SM_RED + 256;
    float* smu   = sm + SM_MU;
    float* srs   = sm + SM_RS;
    int*   idxs  = (int*)(sm + SM_IDX);

    int tid = threadIdx.x;
    int j0  = blockIdx.x * 16;      // global column (b*2048 + ns)
    int b   = j0 >> 11;
    int ns0 = j0 & 2047;

    // merge split-K argmin candidates (earlier chunk wins ties -> matches argmin)
    if (tid < 16) {
        int gs = j0 + tid;
        float bd = g_bestd[gs];
        int   bi = g_besti[gs];
        #pragma unroll
        for (int y = 1; y < 4; ++y) {
            float d2 = g_bestd[y*BNS + gs];
            if (d2 < bd) { bd = d2; bi = g_besti[y*BNS + gs]; }
        }
        idxs[tid] = bi;
    }
    __syncthreads();

    // gather feat columns: Gs[d*16 + j] = feat[b, d, idx_j]
    const float* featb = feat + (size_t)b * DIM * KPTS;
    #pragma unroll 8
    for (int i = tid; i < DIM*16; i += 256) {
        int d = i >> 4, jj = i & 15;
        Gs[i] = __ldg(featb + (size_t)d * KPTS + idxs[jj]);
    }
    __syncthreads();

    unsigned long long acc[8];

    // ---- projection 768 -> 256 ----
    #pragma unroll
    for (int q = 0; q < 8; ++q) acc[q] = 0ULL;
    gemm16(W_proj, DIM, DIM, Gs, Wsm, acc, tid);

    float bb = b_proj[tid];
    {
        float2* xrow = (float2*)(xs + tid*16);
        #pragma unroll
        for (int p = 0; p < 8; ++p) {
            float2 v = unpack2(acc[p]);
            xrow[p] = make_float2(v.x + bb, v.y + bb);
        }
    }
    __syncthreads();

    // ---- LayerNorm over channels (256) per column ----
    {
        int j = tid & 15, part = tid >> 4;
        float s = 0.0f, q2 = 0.0f;
        #pragma unroll
        for (int k = 0; k < 16; ++k) {
            float v = xs[(part*16 + k)*16 + j];
            s += v; q2 += v*v;
        }
        red_s[tid] = s; red_q[tid] = q2;
    }
    __syncthreads();
    if (tid < 16) {
        float S = 0.0f, Q = 0.0f;
        #pragma unroll
        for (int k = 0; k < 16; ++k) { S += red_s[k*16 + tid]; Q += red_q[k*16 + tid]; }
        float mu  = S * (1.0f/256.0f);
        float var = Q * (1.0f/256.0f) - mu*mu;
        smu[tid] = mu;
        srs[tid] = rsqrtf(var + 1e-5f);
    }
    __syncthreads();
    #pragma unroll
    for (int jj = 0; jj < 16; ++jj) {
        float v = xs[tid*16 + jj];
        xs[tid*16 + jj] = (v - smu[jj]) * srs[jj];
    }
    __syncthreads();

    // ---- adapter conv1: 256 -> 256 + ReLU ----
    #pragma unroll
    for (int q = 0; q < 8; ++q) acc[q] = 0ULL;
    gemm16(W_a1, CH, CH, xs, Wsm, acc, tid);
    {
        float bb1 = b_a1[tid];
        float2* hrow = (float2*)(hs + tid*16);
        #pragma unroll
        for (int p = 0; p < 8; ++p) {
            float2 v = unpack2(acc[p]);
            hrow[p] = make_float2(fmaxf(v.x + bb1, 0.0f), fmaxf(v.y + bb1, 0.0f));
        }
    }
    __syncthreads();

    // ---- adapter conv2: 256 -> 256 ----
    #pragma unroll
    for (int q = 0; q < 8; ++q) acc[q] = 0ULL;
    gemm16(W_a2, CH, CH, hs, Wsm, acc, tid);

    float bb2 = b_a2[tid];
    float fv[16];
    #pragma unroll
    for (int p = 0; p < 8; ++p) {
        float2 v = unpack2(acc[p]);
        fv[2*p]   = v.x + bb2;
        fv[2*p+1] = v.y + bb2;
    }

    size_t obase = ((size_t)b * CH + tid) * NSEED + ns0;
    if (NFS <= out_size) {
        float4* o4 = (float4*)(out + obase);
        #pragma unroll
        for (int q = 0; q < 4; ++q)
            o4[q] = make_float4(fv[4*q], fv[4*q+1], fv[4*q+2], fv[4*q+3]);
    }

    // ---- distill loss partial ----
    float ls = 0.0f;
    const float4* t4 = (const float4*)(f_teacher + obase);
    #pragma unroll
    for (int q = 0; q < 4; ++q) {
        float4 t = t4[q];
        float d0 = fv[4*q]   - t.x;
        float d1 = fv[4*q+1] - t.y;
        float d2 = fv[4*q+2] - t.z;
        float d3 = fv[4*q+3] - t.w;
        ls += d0*d0 + d1*d1 + d2*d2 + d3*d3;
    }
    #pragma unroll
    for (int o = 16; o; o >>= 1) ls += __shfl_xor_sync(0xffffffffu, ls, o);
    if ((tid & 31) == 0) atomicAdd(&g_loss, ls);
}

// -------------------- kernel 3: finalize loss --------------------
__global__ void k_final(float* __restrict__ out, int out_size)
{
    float v = g_loss * (1.0f / (float)NFS);
    if (out_size > NFS) {
        for (int i = NFS + (int)threadIdx.x; i < out_size; i += (int)blockDim.x)
            out[i] = v;
    } else if (out_size > 0 && out_size < NFS && threadIdx.x == 0) {
        out[out_size - 1] = v;   // fallback: output carries only the scalar
    }
}

// -------------------- launch --------------------
extern "C" void kernel_launch(void* const* d_in, const int* in_sizes, int n_in,
                              void* d_out, int out_size)
{
    (void)in_sizes; (void)n_in;
    const float* point_cloud = (const float*)d_in[0]; (void)point_cloud; // argmin-invariant
    const float* seed_xyz    = (const float*)d_in[1];
    const float* pts         = (const float*)d_in[2];
    const float* feat        = (const float*)d_in[3];
    const float* f_teacher   = (const float*)d_in[4];
    const float* W_proj      = (const float*)d_in[5];
    const float* b_proj      = (const float*)d_in[6];
    const float* W_a1        = (const float*)d_in[7];
    const float* b_a1        = (const float*)d_in[8];
    const float* W_a2        = (const float*)d_in[9];
    const float* b_a2        = (const float*)d_in[10];
    float* out = (float*)d_out;

    cudaFuncSetAttribute(k_fused, cudaFuncAttributeMaxDynamicSharedMemorySize, SMEM_BYTES);

    k_zero<<<1, 1>>>();
    dim3 g1(BNS/128, 4);
    k_argmin<<<g1, 128>>>(seed_xyz, pts);
    k_fused<<<BNS/16, 256, SMEM_BYTES>>>(feat, f_teacher, W_proj, b_proj,
                                         W_a1, b_a1, W_a2, b_a2, out, out_size);
    k_final<<<1, 64>>>(out, out_size);
}

// round 2
// speedup vs baseline: 1.0667x; 1.0667x over previous
#include <cuda_runtime.h>
#include <cuda_bf16.h>
#include <cstdint>

#define BATCH 8
#define NSEED 2048
#define KPTS  16384
#define DIM   768
#define CH    256
#define BNS   (BATCH*NSEED)              // 16384
#define NFS   (BATCH*CH*NSEED)           // 4194304
#define COLS_T 32                        // columns per fused block
#define THREADS 512

// -------------------- device scratch --------------------
__device__ float g_bestd[4*BNS];
__device__ int   g_besti[4*BNS];
__device__ float g_loss;

__global__ void k_zero() { g_loss = 0.0f; }

// -------------------- kernel 1: split-K argmin (1-NN) --------------------
// Normalization (shared centroid + positive scale) is argmin-invariant; the
// +|s|^2 term is a per-seed constant under monotone rounding -> drop it.
__global__ __launch_bounds__(128) void k_argmin(
    const float* __restrict__ seed, const float* __restrict__ pts)
{
    __shared__ float4 tile[2048];   // {x,y,z,|p|^2}
    int gs = blockIdx.x * 128 + threadIdx.x;
    int b  = gs >> 11;
    int kbase = blockIdx.y * 4096;
    const float* pb = pts + ((size_t)b * KPTS + kbase) * 3;

    float sx = seed[gs*3+0], sy = seed[gs*3+1], sz = seed[gs*3+2];
    float mx = -2.0f*sx, my = -2.0f*sy, mz = -2.0f*sz;

    float bd = 1e30f;
    int   bi = kbase;

    for (int t0 = 0; t0 < 4096; t0 += 2048) {
        for (int p = threadIdx.x; p < 2048; p += 128) {
            float x = pb[(t0+p)*3+0];
            float y = pb[(t0+p)*3+1];
            float z = pb[(t0+p)*3+2];
            tile[p] = make_float4(x, y, z, x*x + y*y + z*z);
        }
        __syncthreads();
        #pragma unroll 8
        for (int p = 0; p < 2048; ++p) {
            float4 v = tile[p];
            float d = fmaf(mx, v.x, fmaf(my, v.y, fmaf(mz, v.z, v.w)));
            if (d < bd) { bd = d; bi = kbase + t0 + p; }
        }
        __syncthreads();
    }
    g_bestd[blockIdx.y * BNS + gs] = bd;
    g_besti[blockIdx.y * BNS + gs] = bi;
}

// -------------------- packed fp32x2 helpers --------------------
__device__ __forceinline__ unsigned long long pack2(float a, float b) {
    unsigned long long r;
    asm("mov.b64 %0, {%1, %2};" : "=l"(r) : "r"(__float_as_uint(a)), "r"(__float_as_uint(b)));
    return r;
}
__device__ __forceinline__ float2 unpack2(unsigned long long v) {
    unsigned int lo, hi;
    asm("mov.b64 {%0, %1}, %2;" : "=r"(lo), "=r"(hi) : "l"(v));
    return make_float2(__uint_as_float(lo), __uint_as_float(hi));
}
__device__ __forceinline__ unsigned long long fma2(unsigned long long a,
                                                   unsigned long long b,
                                                   unsigned long long c) {
    unsigned long long d;
    asm("fma.rn.f32x2 %0, %1, %2, %3;" : "=l"(d) : "l"(a), "l"(b), "l"(c));
    return d;
}

// -------------------- shared memory layout (floats) --------------------
// Gs region (gathered features / activations): 768*32 = 24576
//   xs (padded 256x40) at +0, hs (padded 256x40) at +10240
// W double buffers (transposed, 32 c x 258 pad): 2 x 8256
#define SM_GS    0
#define XS_OFF   0
#define HS_OFF   10240
#define XS_LD    40           // padded row stride (floats) for xs/hs
#define SM_W0    24576
#define SM_W1    (24576 + 8256)
#define SM_RED   41088        // 512 + 512
#define SM_MU    42112
#define SM_RS    42144
#define SM_IDX   42176
#define SMEM_FLOATS 42208
#define SMEM_BYTES  (SMEM_FLOATS * 4)
#define WPAD 258

// D[256 x 32] += W[256 x cdim] * S[cdim x 32]
// Thread: rows (2rp, 2rp+1), cols q*8..q*8+7 (as 4 packed pairs each row).
// W staged transposed into smem (double-buffered via register prefetch).
__device__ __forceinline__ void gemm32(
    const float* __restrict__ W, int ldw, int cdim,
    const unsigned long long* __restrict__ S, int sld,   // stride in ULL
    float* __restrict__ Wb0, float* __restrict__ Wb1,
    unsigned long long acc[8], int tid, int rp, int q)
{
    int nch = cdim >> 5;
    float4 pf[4];
    int seg0 = tid, seg1 = 512 + tid, seg2 = 1024 + tid, seg3 = 1536 + tid;
    int r0 = seg0 >> 3, c40 = (seg0 & 7) * 4;
    int r1 = seg1 >> 3, c41 = (seg1 & 7) * 4;
    int r2 = seg2 >> 3, c42 = (seg2 & 7) * 4;
    int r3 = seg3 >> 3, c43 = (seg3 & 7) * 4;

    pf[0] = *(const float4*)(W + (size_t)r0*ldw + c40);
    pf[1] = *(const float4*)(W + (size_t)r1*ldw + c41);
    pf[2] = *(const float4*)(W + (size_t)r2*ldw + c42);
    pf[3] = *(const float4*)(W + (size_t)r3*ldw + c43);

    for (int k = 0; k < nch; ++k) {
        float* Wb = (k & 1) ? Wb1 : Wb0;
        // stage prefetched chunk (transposed, padded)
        Wb[(c40+0)*WPAD + r0] = pf[0].x; Wb[(c40+1)*WPAD + r0] = pf[0].y;
        Wb[(c40+2)*WPAD + r0] = pf[0].z; Wb[(c40+3)*WPAD + r0] = pf[0].w;
        Wb[(c41+0)*WPAD + r1] = pf[1].x; Wb[(c41+1)*WPAD + r1] = pf[1].y;
        Wb[(c41+2)*WPAD + r1] = pf[1].z; Wb[(c41+3)*WPAD + r1] = pf[1].w;
        Wb[(c42+0)*WPAD + r2] = pf[2].x; Wb[(c42+1)*WPAD + r2] = pf[2].y;
        Wb[(c42+2)*WPAD + r2] = pf[2].z; Wb[(c42+3)*WPAD + r2] = pf[2].w;
        Wb[(c43+0)*WPAD + r3] = pf[3].x; Wb[(c43+1)*WPAD + r3] = pf[3].y;
        Wb[(c43+2)*WPAD + r3] = pf[3].z; Wb[(c43+3)*WPAD + r3] = pf[3].w;
        __syncthreads();
        if (k + 1 < nch) {
            int c0 = (k + 1) << 5;
            pf[0] = *(const float4*)(W + (size_t)r0*ldw + c0 + c40);
            pf[1] = *(const float4*)(W + (size_t)r1*ldw + c0 + c41);
            pf[2] = *(const float4*)(W + (size_t)r2*ldw + c0 + c42);
            pf[3] = *(const float4*)(W + (size_t)r3*ldw + c0 + c43);
        }
        const unsigned long long* Sc = S + (size_t)(k << 5) * sld + q * 4;
        const float* Wr = Wb + 2 * rp;
        #pragma unroll 4
        for (int cc = 0; cc < 32; ++cc) {
            float2 w = *(const float2*)(Wr + cc * WPAD);
            unsigned long long w0 = pack2(w.x, w.x);
            unsigned long long w1 = pack2(w.y, w.y);
            const unsigned long long* sp = Sc + (size_t)cc * sld;
            ulonglong2 sA = *(const ulonglong2*)(sp);
            ulonglong2 sB = *(const ulonglong2*)(sp + 2);
            acc[0] = fma2(w0, sA.x, acc[0]);
            acc[1] = fma2(w0, sA.y, acc[1]);
            acc[2] = fma2(w0, sB.x, acc[2]);
            acc[3] = fma2(w0, sB.y, acc[3]);
            acc[4] = fma2(w1, sA.x, acc[4]);
            acc[5] = fma2(w1, sA.y, acc[5]);
            acc[6] = fma2(w1, sB.x, acc[6]);
            acc[7] = fma2(w1, sB.y, acc[7]);
        }
        __syncthreads();
    }
}

// -------------------- kernel 2: merge + gather + proj + LN + adapters + loss --------------------
__global__ __launch_bounds__(THREADS, 1) void k_fused(
    const float* __restrict__ feat, const float* __restrict__ f_teacher,
    const float* __restrict__ W_proj, const float* __restrict__ b_proj,
    const float* __restrict__ W_a1,   const float* __restrict__ b_a1,
    const float* __restrict__ W_a2,   const float* __restrict__ b_a2,
    float* __restrict__ out, int out_size)
{
    extern __shared__ float sm[];
    float* Gs  = sm + SM_GS;
    float* xs  = sm + XS_OFF;
    float* hs  = sm + HS_OFF;
    float* Wb0 = sm + SM_W0;
    float* Wb1 = sm + SM_W1;
    float* red_s = sm + SM_RED;
    float* red_q = sm + SM_RED + 512;
    float* smu = sm + SM_MU;
    float* srs = sm + SM_RS;
    int*   idxs = (int*)(sm + SM_IDX);

    int tid = threadIdx.x;
    int rp  = tid & 127;          // row pair -> rows 2rp, 2rp+1
    int q   = tid >> 7;           // col quarter -> cols q*8..q*8+7
    int j0  = blockIdx.x * COLS_T;
    int b   = j0 >> 11;
    int ns0 = j0 & 2047;

    // merge split-K argmin candidates
    if (tid < COLS_T) {
        int gs = j0 + tid;
        float bd = g_bestd[gs];
        int   bi = g_besti[gs];
        #pragma unroll
        for (int y = 1; y < 4; ++y) {
            float d2 = g_bestd[y*BNS + gs];
            int   i2 = g_besti[y*BNS + gs];
            if (d2 < bd || (d2 == bd && i2 < bi)) { bd = d2; bi = i2; }
        }
        idxs[tid] = bi;
    }
    __syncthreads();

    // gather feat columns: Gs[d*32 + j] = feat[b, d, idx_j]
    const float* featb = feat + (size_t)b * DIM * KPTS;
    #pragma unroll 8
    for (int i = tid; i < DIM*COLS_T; i += THREADS) {
        int d = i >> 5, jj = i & 31;
        Gs[i] = __ldg(featb + (size_t)d * KPTS + idxs[jj]);
    }
    __syncthreads();

    unsigned long long acc[8];

    // ---- projection 768 -> 256 ----
    #pragma unroll
    for (int p = 0; p < 8; ++p) acc[p] = 0ULL;
    gemm32(W_proj, DIM, DIM, (const unsigned long long*)Gs, 16, Wb0, Wb1, acc, tid, rp, q);

    {   // write x (+bias) into padded xs (overwrites Gs region; gemm ended with sync)
        float bb0 = b_proj[2*rp], bb1 = b_proj[2*rp+1];
        float* x0 = xs + (2*rp)*XS_LD + q*8;
        float* x1 = x0 + XS_LD;
        float2 v0 = unpack2(acc[0]), v1 = unpack2(acc[1]), v2 = unpack2(acc[2]), v3 = unpack2(acc[3]);
        float2 u0 = unpack2(acc[4]), u1 = unpack2(acc[5]), u2 = unpack2(acc[6]), u3 = unpack2(acc[7]);
        ((float4*)x0)[0] = make_float4(v0.x+bb0, v0.y+bb0, v1.x+bb0, v1.y+bb0);
        ((float4*)x0)[1] = make_float4(v2.x+bb0, v2.y+bb0, v3.x+bb0, v3.y+bb0);
        ((float4*)x1)[0] = make_float4(u0.x+bb1, u0.y+bb1, u1.x+bb1, u1.y+bb1);
        ((float4*)x1)[1] = make_float4(u2.x+bb1, u2.y+bb1, u3.x+bb1, u3.y+bb1);
    }
    __syncthreads();

    // ---- LayerNorm over channels (256) per column ----
    {
        int j = tid & 31, g = tid >> 5;         // 16 groups of 16 channels
        float s = 0.0f, q2 = 0.0f;
        #pragma unroll
        for (int k = 0; k < 16; ++k) {
            float v = xs[(g*16 + k)*XS_LD + j];
            s += v; q2 += v*v;
        }
        red_s[tid] = s; red_q[tid] = q2;
    }
    __syncthreads();
    if (tid < COLS_T) {
        float S = 0.0f, Q = 0.0f;
        #pragma unroll
        for (int k = 0; k < 16; ++k) { S += red_s[k*32 + tid]; Q += red_q[k*32 + tid]; }
        float mu  = S * (1.0f/256.0f);
        float var = Q * (1.0f/256.0f) - mu*mu;
        smu[tid] = mu;
        srs[tid] = rsqrtf(var + 1e-5f);
    }
    __syncthreads();
    #pragma unroll 4
    for (int i = tid; i < 256*COLS_T; i += THREADS) {
        int row = i >> 5, col = i & 31;
        float v = xs[row*XS_LD + col];
        xs[row*XS_LD + col] = (v - smu[col]) * srs[col];
    }
    __syncthreads();

    // ---- adapter conv1: 256 -> 256 + ReLU ----
    #pragma unroll
    for (int p = 0; p < 8; ++p) acc[p] = 0ULL;
    gemm32(W_a1, CH, CH, (const unsigned long long*)xs, XS_LD/2, Wb0, Wb1, acc, tid, rp, q);
    {
        float bb0 = b_a1[2*rp], bb1 = b_a1[2*rp+1];
        float* h0 = hs + (2*rp)*XS_LD + q*8;
        float* h1 = h0 + XS_LD;
        float2 v0 = unpack2(acc[0]), v1 = unpack2(acc[1]), v2 = unpack2(acc[2]), v3 = unpack2(acc[3]);
        float2 u0 = unpack2(acc[4]), u1 = unpack2(acc[5]), u2 = unpack2(acc[6]), u3 = unpack2(acc[7]);
        ((float4*)h0)[0] = make_float4(fmaxf(v0.x+bb0,0.f), fmaxf(v0.y+bb0,0.f), fmaxf(v1.x+bb0,0.f), fmaxf(v1.y+bb0,0.f));
        ((float4*)h0)[1] = make_float4(fmaxf(v2.x+bb0,0.f), fmaxf(v2.y+bb0,0.f), fmaxf(v3.x+bb0,0.f), fmaxf(v3.y+bb0,0.f));
        ((float4*)h1)[0] = make_float4(fmaxf(u0.x+bb1,0.f), fmaxf(u0.y+bb1,0.f), fmaxf(u1.x+bb1,0.f), fmaxf(u1.y+bb1,0.f));
        ((float4*)h1)[1] = make_float4(fmaxf(u2.x+bb1,0.f), fmaxf(u2.y+bb1,0.f), fmaxf(u3.x+bb1,0.f), fmaxf(u3.y+bb1,0.f));
    }
    __syncthreads();

    // ---- adapter conv2: 256 -> 256 ----
    #pragma unroll
    for (int p = 0; p < 8; ++p) acc[p] = 0ULL;
    gemm32(W_a2, CH, CH, (const unsigned long long*)hs, XS_LD/2, Wb0, Wb1, acc, tid, rp, q);

    float bb0 = b_a2[2*rp], bb1 = b_a2[2*rp+1];
    float fv[16];
    {
        float2 v0 = unpack2(acc[0]), v1 = unpack2(acc[1]), v2 = unpack2(acc[2]), v3 = unpack2(acc[3]);
        float2 u0 = unpack2(acc[4]), u1 = unpack2(acc[5]), u2 = unpack2(acc[6]), u3 = unpack2(acc[7]);
        fv[0]=v0.x+bb0; fv[1]=v0.y+bb0; fv[2]=v1.x+bb0; fv[3]=v1.y+bb0;
        fv[4]=v2.x+bb0; fv[5]=v2.y+bb0; fv[6]=v3.x+bb0; fv[7]=v3.y+bb0;
        fv[8]=u0.x+bb1; fv[9]=u0.y+bb1; fv[10]=u1.x+bb1; fv[11]=u1.y+bb1;
        fv[12]=u2.x+bb1; fv[13]=u2.y+bb1; fv[14]=u3.x+bb1; fv[15]=u3.y+bb1;
    }

    size_t o0 = ((size_t)b * CH + 2*rp) * NSEED + ns0 + q*8;
    size_t o1 = o0 + NSEED;
    if (NFS <= out_size) {
        ((float4*)(out + o0))[0] = make_float4(fv[0], fv[1], fv[2], fv[3]);
        ((float4*)(out + o0))[1] = make_float4(fv[4], fv[5], fv[6], fv[7]);
        ((float4*)(out + o1))[0] = make_float4(fv[8], fv[9], fv[10], fv[11]);
        ((float4*)(out + o1))[1] = make_float4(fv[12], fv[13], fv[14], fv[15]);
    }

    // ---- distill loss partial ----
    float ls = 0.0f;
    {
        const float4* t0 = (const float4*)(f_teacher + o0);
        const float4* t1 = (const float4*)(f_teacher + o1);
        #pragma unroll
        for (int p = 0; p < 2; ++p) {
            float4 t = t0[p];
            float d0 = fv[4*p]-t.x, d1 = fv[4*p+1]-t.y, d2 = fv[4*p+2]-t.z, d3 = fv[4*p+3]-t.w;
            ls += d0*d0 + d1*d1 + d2*d2 + d3*d3;
        }
        #pragma unroll
        for (int p = 0; p < 2; ++p) {
            float4 t = t1[p];
            float d0 = fv[8+4*p]-t.x, d1 = fv[8+4*p+1]-t.y, d2 = fv[8+4*p+2]-t.z, d3 = fv[8+4*p+3]-t.w;
            ls += d0*d0 + d1*d1 + d2*d2 + d3*d3;
        }
    }
    #pragma unroll
    for (int o = 16; o; o >>= 1) ls += __shfl_xor_sync(0xffffffffu, ls, o);
    if ((tid & 31) == 0) atomicAdd(&g_loss, ls);
}

// -------------------- kernel 3: finalize loss --------------------
__global__ void k_final(float* __restrict__ out, int out_size)
{
    float v = g_loss * (1.0f / (float)NFS);
    if (out_size > NFS) {
        for (int i = NFS + (int)threadIdx.x; i < out_size; i += (int)blockDim.x)
            out[i] = v;
    } else if (out_size > 0 && out_size < NFS && threadIdx.x == 0) {
        out[out_size - 1] = v;
    }
}

// -------------------- launch --------------------
extern "C" void kernel_launch(void* const* d_in, const int* in_sizes, int n_in,
                              void* d_out, int out_size)
{
    (void)in_sizes; (void)n_in;
    const float* seed_xyz    = (const float*)d_in[1];
    const float* pts         = (const float*)d_in[2];
    const float* feat        = (const float*)d_in[3];
    const float* f_teacher   = (const float*)d_in[4];
    const float* W_proj      = (const float*)d_in[5];
    const float* b_proj      = (const float*)d_in[6];
    const float* W_a1        = (const float*)d_in[7];
    const float* b_a1        = (const float*)d_in[8];
    const float* W_a2        = (const float*)d_in[9];
    const float* b_a2        = (const float*)d_in[10];
    float* out = (float*)d_out;

    cudaFuncSetAttribute(k_fused, cudaFuncAttributeMaxDynamicSharedMemorySize, SMEM_BYTES);

    k_zero<<<1, 1>>>();
    dim3 g1(BNS/128, 4);
    k_argmin<<<g1, 128>>>(seed_xyz, pts);
    k_fused<<<BNS/COLS_T, THREADS, SMEM_BYTES>>>(feat, f_teacher, W_proj, b_proj,
                                                 W_a1, b_a1, W_a2, b_a2, out, out_size);
    k_final<<<1, 64>>>(out, out_size);
}

// round 4
// speedup vs baseline: 1.6020x; 1.5019x over previous
#include <cuda_runtime.h>
#include <cuda_bf16.h>
#include <cstdint>

#define BATCH 8
#define NSEED 2048
#define KPTS  16384
#define DIM   768
#define CH    256
#define BNS   (BATCH*NSEED)              // 16384
#define NFS   (BATCH*CH*NSEED)           // 4194304
#define COLS_T 32
#define THREADS 512
#define NKS_P 144     // proj k-steps   (K' = 3*768 = 2304)
#define NKS_A 48      // adapter k-steps (K' = 3*256 = 768)
#define NTILES 4      // 32 cols / n8

typedef unsigned short ushort_t;

// -------------------- device scratch --------------------
__device__ float g_bestd[4*BNS];
__device__ int   g_besti[4*BNS];
__device__ float g_loss;
// fragment-permuted bf16 weights, halfword granularity
__device__ ushort_t g_Ap [16*NKS_P*32*4*2];   // 1.18 MB
__device__ ushort_t g_Aa1[16*NKS_A*32*4*2];   // 393 KB
__device__ ushort_t g_Aa2[16*NKS_A*32*4*2];

__global__ void k_zero() { g_loss = 0.0f; }

// -------------------- hi/lo split --------------------
__device__ __forceinline__ void split_hilo(float x, ushort_t& h, ushort_t& l) {
    __nv_bfloat16 hb = __float2bfloat16(x);
    __nv_bfloat16 lb = __float2bfloat16(x - __bfloat162float(hb));
    h = __bfloat16_as_ushort(hb);
    l = __bfloat16_as_ushort(lb);
}

// A halfword index for K' slot s, output row o
__device__ __forceinline__ size_t aidx_h(int o, int s, int nks) {
    int kstep = s >> 4, ks = s & 15;
    int mtile = o >> 4, mm = o & 15;
    int lane = (mm & 7) * 4 + ((ks >> 1) & 3);
    int word = ((mm >> 3) & 1) + 2 * ((ks >> 3) & 1);
    int half = ks & 1;
    return ((((size_t)mtile * nks + kstep) * 32 + lane) * 4 + word) * 2 + half;
}

// B halfword index for K' slot s, column n
__device__ __forceinline__ int bidx_h(int s, int n) {
    int kstep = s >> 4, ks = s & 15;
    int ntile = n >> 3;
    int lane = (n & 7) * 4 + ((ks >> 1) & 3);
    int wk = (ks >> 3) & 1;
    int half = ks & 1;
    return (((kstep * NTILES + ntile) * 32 + lane) * 2 + wk) * 2 + half;
}

// slots per element d: A = [hi, hi, lo], B = [hi, lo, hi]  ->  hh + hl + lh
__device__ __forceinline__ void put_A(ushort_t* arr, int o, int d, int nks, float w) {
    ushort_t h, l; split_hilo(w, h, l);
    arr[aidx_h(o, 3*d+0, nks)] = h;
    arr[aidx_h(o, 3*d+1, nks)] = h;
    arr[aidx_h(o, 3*d+2, nks)] = l;
}

// -------------------- weight prep kernel --------------------
__global__ __launch_bounds__(256) void k_prep(
    const float* __restrict__ Wp, const float* __restrict__ Wa1, const float* __restrict__ Wa2)
{
    int id = blockIdx.x * 256 + threadIdx.x;
    if (id < 256*768) {
        int o = id / 768, d = id % 768;
        put_A(g_Ap, o, d, NKS_P, Wp[id]);
    } else if (id < 256*768 + 256*256) {
        int t = id - 256*768; int o = t >> 8, d = t & 255;
        put_A(g_Aa1, o, d, NKS_A, Wa1[t]);
    } else if (id < 256*768 + 2*256*256) {
        int t = id - 256*768 - 256*256; int o = t >> 8, d = t & 255;
        put_A(g_Aa2, o, d, NKS_A, Wa2[t]);
    }
}

// -------------------- kernel 1: split-K argmin (unchanged, exact fp32) --------------------
__global__ __launch_bounds__(128) void k_argmin(
    const float* __restrict__ seed, const float* __restrict__ pts)
{
    __shared__ float4 tile[2048];
    int gs = blockIdx.x * 128 + threadIdx.x;
    int b  = gs >> 11;
    int kbase = blockIdx.y * 4096;
    const float* pb = pts + ((size_t)b * KPTS + kbase) * 3;

    float sx = seed[gs*3+0], sy = seed[gs*3+1], sz = seed[gs*3+2];
    float mx = -2.0f*sx, my = -2.0f*sy, mz = -2.0f*sz;

    float bd = 1e30f;
    int   bi = kbase;

    for (int t0 = 0; t0 < 4096; t0 += 2048) {
        for (int p = threadIdx.x; p < 2048; p += 128) {
            float x = pb[(t0+p)*3+0];
            float y = pb[(t0+p)*3+1];
            float z = pb[(t0+p)*3+2];
            tile[p] = make_float4(x, y, z, x*x + y*y + z*z);
        }
        __syncthreads();
        #pragma unroll 8
        for (int p = 0; p < 2048; ++p) {
            float4 v = tile[p];
            float d = fmaf(mx, v.x, fmaf(my, v.y, fmaf(mz, v.z, v.w)));
            if (d < bd) { bd = d; bi = kbase + t0 + p; }
        }
        __syncthreads();
    }
    g_bestd[blockIdx.y * BNS + gs] = bd;
    g_besti[blockIdx.y * BNS + gs] = bi;
}

// -------------------- mma.sync helper --------------------
__device__ __forceinline__ void mma16816(float* c, const uint4& a, const uint2& b) {
    asm volatile(
        "mma.sync.aligned.m16n8k16.row.col.f32.bf16.bf16.f32 "
        "{%0,%1,%2,%3}, {%4,%5,%6,%7}, {%8,%9}, {%0,%1,%2,%3};"
        : "+f"(c[0]), "+f"(c[1]), "+f"(c[2]), "+f"(c[3])
        : "r"(a.x), "r"(a.y), "r"(a.z), "r"(a.w), "r"(b.x), "r"(b.y));
}

// -------------------- shared memory layout (bytes) --------------------
#define XS_LD    34
#define SMB_BP   0          // proj B-perm: 147456 B (union region)
#define SMB_XS   0          // xs fp32 256*34*4 = 34816
#define SMB_BA   40960      // adapter1 B-perm: 49152 -> ends 90112
#define SMB_BH   90112      // adapter2 B-perm: 49152 -> ends 139264
#define SMB_RED  147456     // red_s 2048 + red_q 2048
#define SMB_MU   151552
#define SMB_RS   151680
#define SMB_IDX  151808
#define SMEM_BYTES 151936

// -------------------- kernel 2: fused tensor-core pipeline --------------------
__global__ __launch_bounds__(THREADS, 1) void k_fused(
    const float* __restrict__ feat, const float* __restrict__ f_teacher,
    const float* __restrict__ b_proj, const float* __restrict__ b_a1,
    const float* __restrict__ b_a2,
    float* __restrict__ out, int out_size)
{
    extern __shared__ char smraw[];
    ushort_t* Bp   = (ushort_t*)(smraw + SMB_BP);
    float*    xs   = (float*)(smraw + SMB_XS);
    ushort_t* Ba   = (ushort_t*)(smraw + SMB_BA);
    ushort_t* Bh   = (ushort_t*)(smraw + SMB_BH);
    float*    red_s= (float*)(smraw + SMB_RED);
    float*    red_q= (float*)(smraw + SMB_RED + 2048);
    float*    smu  = (float*)(smraw + SMB_MU);
    float*    srs  = (float*)(smraw + SMB_RS);
    int*      idxs = (int*)(smraw + SMB_IDX);

    int tid  = threadIdx.x;
    int lane = tid & 31;
    int wid  = tid >> 5;                 // warp = m-tile
    int j0   = blockIdx.x * COLS_T;
    int b    = j0 >> 11;
    int ns0  = j0 & 2047;

    // ---- merge split-K argmin candidates ----
    if (tid < COLS_T) {
        int gs = j0 + tid;
        float bd = g_bestd[gs];
        int   bi = g_besti[gs];
        #pragma unroll
        for (int y = 1; y < 4; ++y) {
            float d2 = g_bestd[y*BNS + gs];
            int   i2 = g_besti[y*BNS + gs];
            if (d2 < bd || (d2 == bd && i2 < bi)) { bd = d2; bi = i2; }
        }
        idxs[tid] = bi;
    }
    __syncthreads();

    // ---- gather + convert to 3-term hi/lo fragment layout ----
    const float* featb = feat + (size_t)b * DIM * KPTS;
    #pragma unroll 4
    for (int i = tid; i < DIM*COLS_T; i += THREADS) {
        int d = i >> 5, jj = i & 31;
        float x = __ldg(featb + (size_t)d * KPTS + idxs[jj]);
        ushort_t h, l; split_hilo(x, h, l);
        Bp[bidx_h(3*d+0, jj)] = h;
        Bp[bidx_h(3*d+1, jj)] = l;
        Bp[bidx_h(3*d+2, jj)] = h;
    }
    __syncthreads();

    int r  = lane >> 2;
    int c2 = (lane & 3) * 2;
    int m0 = wid * 16;

    float acc[16];
    #pragma unroll
    for (int p = 0; p < 16; ++p) acc[p] = 0.0f;

    // ---- projection 768->256 (K' = 2304) ----
    {
        const uint4* Apw = (const uint4*)g_Ap + ((size_t)wid*NKS_P*32 + lane);
        const uint2* Bpw = (const uint2*)Bp + lane;
        #pragma unroll 4
        for (int ks = 0; ks < NKS_P; ++ks) {
            uint4 a = Apw[ks*32];
            #pragma unroll
            for (int nt = 0; nt < NTILES; ++nt) {
                uint2 bw = Bpw[(ks*NTILES + nt)*32];
                mma16816(acc + nt*4, a, bw);
            }
        }
    }
    __syncthreads();   // Bp consumed before xs overwrite

    // ---- bias + write x to smem ----
    {
        float bb0 = __ldg(b_proj + m0 + r);
        float bb1 = __ldg(b_proj + m0 + r + 8);
        #pragma unroll
        for (int nt = 0; nt < NTILES; ++nt) {
            int col = nt*8 + c2;
            *(float2*)(xs + (m0+r)*XS_LD + col)   = make_float2(acc[nt*4+0]+bb0, acc[nt*4+1]+bb0);
            *(float2*)(xs + (m0+r+8)*XS_LD + col) = make_float2(acc[nt*4+2]+bb1, acc[nt*4+3]+bb1);
        }
    }
    __syncthreads();

    // ---- LayerNorm stats ----
    {
        int j = tid & 31, g = tid >> 5;
        float s = 0.0f, q2 = 0.0f;
        #pragma unroll
        for (int k = 0; k < 16; ++k) {
            float v = xs[(g*16 + k)*XS_LD + j];
            s += v; q2 += v*v;
        }
        red_s[tid] = s; red_q[tid] = q2;
    }
    __syncthreads();
    if (tid < COLS_T) {
        float S = 0.0f, Q = 0.0f;
        #pragma unroll
        for (int k = 0; k < 16; ++k) { S += red_s[k*32 + tid]; Q += red_q[k*32 + tid]; }
        float mu  = S * (1.0f/256.0f);
        float var = Q * (1.0f/256.0f) - mu*mu;
        smu[tid] = mu;
        srs[tid] = rsqrtf(var + 1e-5f);
    }
    __syncthreads();

    // ---- normalize + convert into adapter B layout ----
    #pragma unroll 4
    for (int i = tid; i < 256*COLS_T; i += THREADS) {
        int row = i >> 5, col = i & 31;
        float v = (xs[row*XS_LD + col] - smu[col]) * srs[col];
        ushort_t h, l; split_hilo(v, h, l);
        Ba[bidx_h(3*row+0, col)] = h;
        Ba[bidx_h(3*row+1, col)] = l;
        Ba[bidx_h(3*row+2, col)] = h;
    }
    __syncthreads();

    // ---- adapter conv1 (K' = 768) + ReLU -> Bh ----
    #pragma unroll
    for (int p = 0; p < 16; ++p) acc[p] = 0.0f;
    {
        const uint4* Aw = (const uint4*)g_Aa1 + ((size_t)wid*NKS_A*32 + lane);
        const uint2* Baw = (const uint2*)Ba + lane;
        #pragma unroll 4
        for (int ks = 0; ks < NKS_A; ++ks) {
            uint4 a = Aw[ks*32];
            #pragma unroll
            for (int nt = 0; nt < NTILES; ++nt) {
                uint2 bw = Baw[(ks*NTILES + nt)*32];
                mma16816(acc + nt*4, a, bw);
            }
        }
    }
    {
        float bb0 = __ldg(b_a1 + m0 + r);
        float bb1 = __ldg(b_a1 + m0 + r + 8);
        #pragma unroll
        for (int nt = 0; nt < NTILES; ++nt) {
            int col = nt*8 + c2;
            float v0 = fmaxf(acc[nt*4+0]+bb0, 0.0f);
            float v1 = fmaxf(acc[nt*4+1]+bb0, 0.0f);
            float v2 = fmaxf(acc[nt*4+2]+bb1, 0.0f);
            float v3 = fmaxf(acc[nt*4+3]+bb1, 0.0f);
            ushort_t h, l;
            split_hilo(v0, h, l);
            Bh[bidx_h(3*(m0+r)+0, col)]   = h; Bh[bidx_h(3*(m0+r)+1, col)]   = l; Bh[bidx_h(3*(m0+r)+2, col)]   = h;
            split_hilo(v1, h, l);
            Bh[bidx_h(3*(m0+r)+0, col+1)] = h; Bh[bidx_h(3*(m0+r)+1, col+1)] = l; Bh[bidx_h(3*(m0+r)+2, col+1)] = h;
            split_hilo(v2, h, l);
            Bh[bidx_h(3*(m0+r+8)+0, col)] = h; Bh[bidx_h(3*(m0+r+8)+1, col)] = l; Bh[bidx_h(3*(m0+r+8)+2, col)] = h;
            split_hilo(v3, h, l);
            Bh[bidx_h(3*(m0+r+8)+0, col+1)] = h; Bh[bidx_h(3*(m0+r+8)+1, col+1)] = l; Bh[bidx_h(3*(m0+r+8)+2, col+1)] = h;
        }
    }
    __syncthreads();

    // ---- adapter conv2 (K' = 768) ----
    #pragma unroll
    for (int p = 0; p < 16; ++p) acc[p] = 0.0f;
    {
        const uint4* Aw = (const uint4*)g_Aa2 + ((size_t)wid*NKS_A*32 + lane);
        const uint2* Bhw = (const uint2*)Bh + lane;
        #pragma unroll 4
        for (int ks = 0; ks < NKS_A; ++ks) {
            uint4 a = Aw[ks*32];
            #pragma unroll
            for (int nt = 0; nt < NTILES; ++nt) {
                uint2 bw = Bhw[(ks*NTILES + nt)*32];
                mma16816(acc + nt*4, a, bw);
            }
        }
    }

    // ---- bias + output + loss ----
    float bb0 = __ldg(b_a2 + m0 + r);
    float bb1 = __ldg(b_a2 + m0 + r + 8);
    float ls = 0.0f;
    size_t ob0 = ((size_t)b * CH + (m0 + r)) * NSEED + ns0;
    size_t ob1 = ((size_t)b * CH + (m0 + r + 8)) * NSEED + ns0;
    bool full = (NFS <= out_size);
    #pragma unroll
    for (int nt = 0; nt < NTILES; ++nt) {
        int col = nt*8 + c2;
        float f0 = acc[nt*4+0]+bb0, f1 = acc[nt*4+1]+bb0;
        float f2 = acc[nt*4+2]+bb1, f3 = acc[nt*4+3]+bb1;
        if (full) {
            *(float2*)(out + ob0 + col) = make_float2(f0, f1);
            *(float2*)(out + ob1 + col) = make_float2(f2, f3);
        }
        float2 t0 = *(const float2*)(f_teacher + ob0 + col);
        float2 t1 = *(const float2*)(f_teacher + ob1 + col);
        float d0 = f0-t0.x, d1 = f1-t0.y, d2 = f2-t1.x, d3 = f3-t1.y;
        ls += d0*d0 + d1*d1 + d2*d2 + d3*d3;
    }
    #pragma unroll
    for (int o = 16; o; o >>= 1) ls += __shfl_xor_sync(0xffffffffu, ls, o);
    if (lane == 0) atomicAdd(&g_loss, ls);
}

// -------------------- kernel 3: finalize loss --------------------
__global__ void k_final(float* __restrict__ out, int out_size)
{
    float v = g_loss * (1.0f / (float)NFS);
    if (out_size > NFS) {
        for (int i = NFS + (int)threadIdx.x; i < out_size; i += (int)blockDim.x)
            out[i] = v;
    } else if (out_size > 0 && out_size < NFS && threadIdx.x == 0) {
        out[out_size - 1] = v;
    }
}

// -------------------- launch --------------------
extern "C" void kernel_launch(void* const* d_in, const int* in_sizes, int n_in,
                              void* d_out, int out_size)
{
    (void)in_sizes; (void)n_in;
    const float* seed_xyz    = (const float*)d_in[1];
    const float* pts         = (const float*)d_in[2];
    const float* feat        = (const float*)d_in[3];
    const float* f_teacher   = (const float*)d_in[4];
    const float* W_proj      = (const float*)d_in[5];
    const float* b_proj      = (const float*)d_in[6];
    const float* W_a1        = (const float*)d_in[7];
    const float* b_a1        = (const float*)d_in[8];
    const float* W_a2        = (const float*)d_in[9];
    const float* b_a2        = (const float*)d_in[10];
    float* out = (float*)d_out;

    cudaFuncSetAttribute(k_fused, cudaFuncAttributeMaxDynamicSharedMemorySize, SMEM_BYTES);

    k_zero<<<1, 1>>>();
    k_prep<<<(256*768 + 2*256*256 + 255)/256, 256>>>(W_proj, W_a1, W_a2);
    dim3 g1(BNS/128, 4);
    k_argmin<<<g1, 128>>>(seed_xyz, pts);
    k_fused<<<BNS/COLS_T, THREADS, SMEM_BYTES>>>(feat, f_teacher,
                                                 b_proj, b_a1, b_a2, out, out_size);
    k_final<<<1, 64>>>(out, out_size);
}

// round 5
// speedup vs baseline: 1.7089x; 1.0667x over previous
#include <cuda_runtime.h>
#include <cuda_bf16.h>
#include <cstdint>

#define BATCH 8
#define NSEED 2048
#define KPTS  16384
#define DIM   768
#define CH    256
#define BNS   (BATCH*NSEED)
#define NFS   (BATCH*CH*NSEED)
#define COLS_T 32
#define THREADS 512
#define NKS_P 144     // proj k-steps (K' = 2304)
#define NKS_A 48      // adapter k-steps (K' = 768)
#define NTILES 4
#define CHKS 48       // ksteps per proj chunk (= 256 dims)
#define CHDIM 256

typedef unsigned short ushort_t;

// -------------------- device scratch --------------------
__device__ float g_bestd[4*BNS];
__device__ int   g_besti[4*BNS];
__device__ float g_loss;
__device__ ushort_t g_Ap [16*NKS_P*32*4*2];
__device__ ushort_t g_Aa1[16*NKS_A*32*4*2];
__device__ ushort_t g_Aa2[16*NKS_A*32*4*2];

__global__ void k_zero() { g_loss = 0.0f; }

// -------------------- helpers --------------------
__device__ __forceinline__ void split_hilo(float x, ushort_t& h, ushort_t& l) {
    __nv_bfloat16 hb = __float2bfloat16(x);
    __nv_bfloat16 lb = __float2bfloat16(x - __bfloat162float(hb));
    h = __bfloat16_as_ushort(hb);
    l = __bfloat16_as_ushort(lb);
}
__device__ __forceinline__ unsigned long long pack2(float a, float b) {
    unsigned long long r;
    asm("mov.b64 %0, {%1, %2};" : "=l"(r) : "r"(__float_as_uint(a)), "r"(__float_as_uint(b)));
    return r;
}
__device__ __forceinline__ float2 unpack2(unsigned long long v) {
    unsigned int lo, hi;
    asm("mov.b64 {%0, %1}, %2;" : "=r"(lo), "=r"(hi) : "l"(v));
    return make_float2(__uint_as_float(lo), __uint_as_float(hi));
}
__device__ __forceinline__ unsigned long long fma2(unsigned long long a,
                                                   unsigned long long b,
                                                   unsigned long long c) {
    unsigned long long d;
    asm("fma.rn.f32x2 %0, %1, %2, %3;" : "=l"(d) : "l"(a), "l"(b), "l"(c));
    return d;
}

__device__ __forceinline__ size_t aidx_h(int o, int s, int nks) {
    int kstep = s >> 4, ks = s & 15;
    int mtile = o >> 4, mm = o & 15;
    int lane = (mm & 7) * 4 + ((ks >> 1) & 3);
    int word = ((mm >> 3) & 1) + 2 * ((ks >> 3) & 1);
    int half = ks & 1;
    return ((((size_t)mtile * nks + kstep) * 32 + lane) * 4 + word) * 2 + half;
}
__device__ __forceinline__ int bidx_h(int s, int n) {
    int kstep = s >> 4, ks = s & 15;
    int ntile = n >> 3;
    int lane = (n & 7) * 4 + ((ks >> 1) & 3);
    int wk = (ks >> 3) & 1;
    int half = ks & 1;
    return (((kstep * NTILES + ntile) * 32 + lane) * 2 + wk) * 2 + half;
}
__device__ __forceinline__ void put3(ushort_t* buf, int row, int col, float v) {
    ushort_t h, l; split_hilo(v, h, l);
    int s0 = 3*row;
    buf[bidx_h(s0,   col)] = h;
    buf[bidx_h(s0+1, col)] = l;
    buf[bidx_h(s0+2, col)] = h;
}
__device__ __forceinline__ void put_A(ushort_t* arr, int o, int d, int nks, float w) {
    ushort_t h, l; split_hilo(w, h, l);
    arr[aidx_h(o, 3*d+0, nks)] = h;
    arr[aidx_h(o, 3*d+1, nks)] = h;
    arr[aidx_h(o, 3*d+2, nks)] = l;
}

// -------------------- weight prep --------------------
__global__ __launch_bounds__(256) void k_prep(
    const float* __restrict__ Wp, const float* __restrict__ Wa1, const float* __restrict__ Wa2)
{
    int id = blockIdx.x * 256 + threadIdx.x;
    if (id < 256*768) {
        int o = id / 768, d = id % 768;
        put_A(g_Ap, o, d, NKS_P, Wp[id]);
    } else if (id < 256*768 + 256*256) {
        int t = id - 256*768; int o = t >> 8, d = t & 255;
        put_A(g_Aa1, o, d, NKS_A, Wa1[t]);
    } else if (id < 256*768 + 2*256*256) {
        int t = id - 256*768 - 256*256; int o = t >> 8, d = t & 255;
        put_A(g_Aa2, o, d, NKS_A, Wa2[t]);
    }
}

// -------------------- kernel 1: split-K argmin, f32x2 distances --------------------
__global__ __launch_bounds__(128) void k_argmin(
    const float* __restrict__ seed, const float* __restrict__ pts)
{
    __shared__ float4 tA[1024], tB[1024];   // pairs: (x0,x1,y0,y1), (z0,z1,w0,w1)
    int gs = blockIdx.x * 128 + threadIdx.x;
    int b  = gs >> 11;
    int kbase = blockIdx.y * 4096;
    const float* pb = pts + ((size_t)b * KPTS + kbase) * 3;

    float sx = seed[gs*3+0], sy = seed[gs*3+1], sz = seed[gs*3+2];
    unsigned long long mxx = pack2(-2.0f*sx, -2.0f*sx);
    unsigned long long myy = pack2(-2.0f*sy, -2.0f*sy);
    unsigned long long mzz = pack2(-2.0f*sz, -2.0f*sz);

    float bd = 1e30f;
    int   bi = kbase;

    for (int t0 = 0; t0 < 4096; t0 += 2048) {
        for (int p = threadIdx.x; p < 1024; p += 128) {
            const float* q = pb + (t0 + 2*p)*3;
            float x0=q[0], y0=q[1], z0=q[2], x1=q[3], y1=q[4], z1=q[5];
            tA[p] = make_float4(x0, x1, y0, y1);
            tB[p] = make_float4(z0, z1, x0*x0+y0*y0+z0*z0, x1*x1+y1*y1+z1*z1);
        }
        __syncthreads();
        #pragma unroll 8
        for (int p = 0; p < 1024; ++p) {
            float4 A = tA[p], B = tB[p];
            unsigned long long d2 =
                fma2(mxx, pack2(A.x, A.y),
                fma2(myy, pack2(A.z, A.w),
                fma2(mzz, pack2(B.x, B.y), pack2(B.z, B.w))));
            float2 d = unpack2(d2);
            if (d.x < bd) { bd = d.x; bi = kbase + t0 + 2*p; }
            if (d.y < bd) { bd = d.y; bi = kbase + t0 + 2*p + 1; }
        }
        __syncthreads();
    }
    g_bestd[blockIdx.y * BNS + gs] = bd;
    g_besti[blockIdx.y * BNS + gs] = bi;
}

// -------------------- mma helpers --------------------
__device__ __forceinline__ void mma16816(float* c, const uint4& a, const uint2& b) {
    asm volatile(
        "mma.sync.aligned.m16n8k16.row.col.f32.bf16.bf16.f32 "
        "{%0,%1,%2,%3}, {%4,%5,%6,%7}, {%8,%9}, {%0,%1,%2,%3};"
        : "+f"(c[0]), "+f"(c[1]), "+f"(c[2]), "+f"(c[3])
        : "r"(a.x), "r"(a.y), "r"(a.z), "r"(a.w), "r"(b.x), "r"(b.y));
}
__device__ __forceinline__ void mma_span(float acc[16],
    const uint4* __restrict__ Aw, const uint2* __restrict__ Bw, int ks0, int ks1)
{
    #pragma unroll 4
    for (int ks = ks0; ks < ks1; ++ks) {
        uint4 a = Aw[(size_t)ks*32];
        #pragma unroll
        for (int nt = 0; nt < NTILES; ++nt) {
            uint2 bw = Bw[(ks*NTILES + nt)*32];
            mma16816(acc + nt*4, a, bw);
        }
    }
}

// -------------------- smem layout --------------------
// buf0 [0, 49152), buf1 [49152, 98304)  -- 48-kstep fragment buffers
// red_s/red_q alias buf1 (dead window); smu/srs/idxs at tail
#define SMB_BUF1 49152
#define SMB_MU   98304
#define SMB_RS   98432
#define SMB_IDX  98560
#define SMEM_BYTES 98816

// -------------------- kernel 2: fused --------------------
__global__ void __launch_bounds__(THREADS, 2) k_fused(
    const float* __restrict__ feat, const float* __restrict__ f_teacher,
    const float* __restrict__ b_proj, const float* __restrict__ b_a1,
    const float* __restrict__ b_a2,
    float* __restrict__ out, int out_size)
{
    extern __shared__ char smraw[];
    ushort_t* buf0 = (ushort_t*)smraw;
    ushort_t* buf1 = (ushort_t*)(smraw + SMB_BUF1);
    float* red_s = (float*)(smraw + SMB_BUF1);          // alias buf1
    float* red_q = (float*)(smraw + SMB_BUF1 + 2048);
    float* smu   = (float*)(smraw + SMB_MU);
    float* srs   = (float*)(smraw + SMB_RS);
    int*   idxs  = (int*)(smraw + SMB_IDX);

    int tid  = threadIdx.x;
    int lane = tid & 31;
    int wid  = tid >> 5;
    int j0   = blockIdx.x * COLS_T;
    int b    = j0 >> 11;
    int ns0  = j0 & 2047;

    if (tid < COLS_T) {
        int gs = j0 + tid;
        float bd = g_bestd[gs];
        int   bi = g_besti[gs];
        #pragma unroll
        for (int y = 1; y < 4; ++y) {
            float d2 = g_bestd[y*BNS + gs];
            int   i2 = g_besti[y*BNS + gs];
            if (d2 < bd || (d2 == bd && i2 < bi)) { bd = d2; bi = i2; }
        }
        idxs[tid] = bi;
    }
    __syncthreads();

    // per-thread gather geometry: col is FIXED (= lane), dims stride 16
    const float* featb = feat + (size_t)b * DIM * KPTS;
    int mycol = tid & 31;
    int drow  = tid >> 5;                 // 0..15
    const float* gbase = featb + idxs[mycol];

    // ---- chunk 0 gather -> buf0 ----
    {
        float v[16];
        #pragma unroll
        for (int t = 0; t < 16; ++t)
            v[t] = __ldg(gbase + (size_t)(drow + t*16) * KPTS);
        #pragma unroll
        for (int t = 0; t < 16; ++t)
            put3(buf0, drow + t*16, mycol, v[t]);   // local row within chunk
    }
    __syncthreads();

    int r  = lane >> 2;
    int c2 = (lane & 3) * 2;
    int m0 = wid * 16;

    float acc[16];
    #pragma unroll
    for (int p = 0; p < 16; ++p) acc[p] = 0.0f;

    const uint4* Apw = (const uint4*)g_Ap + ((size_t)wid*NKS_P*32 + lane);
    const uint2* B0  = (const uint2*)buf0 + lane;
    const uint2* B1  = (const uint2*)buf1 + lane;

    // ---- projection: 3 chunks, pipelined gather ----
    #pragma unroll 1
    for (int c = 0; c < 3; ++c) {
        const uint2* Bw  = (c & 1) ? B1 : B0;
        ushort_t*    nbf = (c & 1) ? buf0 : buf1;
        const uint4* Aw  = Apw + (size_t)c*CHKS*32;
        bool more = (c < 2);
        int nb = (c+1)*CHDIM;
        float st[8];
        if (more) {
            #pragma unroll
            for (int t = 0; t < 8; ++t)
                st[t] = __ldg(gbase + (size_t)(nb + drow + t*16) * KPTS);
        }
        mma_span(acc, Aw, Bw, 0, 24);
        if (more) {
            #pragma unroll
            for (int t = 0; t < 8; ++t)
                put3(nbf, drow + t*16, mycol, st[t]);
            #pragma unroll
            for (int t = 0; t < 8; ++t)
                st[t] = __ldg(gbase + (size_t)(nb + drow + (8+t)*16) * KPTS);
        }
        mma_span(acc, Aw, Bw, 24, 48);
        if (more) {
            #pragma unroll
            for (int t = 0; t < 8; ++t)
                put3(nbf, drow + (8+t)*16, mycol, st[t]);
        }
        __syncthreads();
    }

    // ---- bias + LN stats in registers ----
    {
        float bb0 = __ldg(b_proj + m0 + r);
        float bb1 = __ldg(b_proj + m0 + r + 8);
        #pragma unroll
        for (int nt = 0; nt < NTILES; ++nt) {
            acc[nt*4+0] += bb0; acc[nt*4+1] += bb0;
            acc[nt*4+2] += bb1; acc[nt*4+3] += bb1;
        }
    }
    {
        float s[8], q[8];
        #pragma unroll
        for (int nt = 0; nt < NTILES; ++nt) {
            s[nt*2+0] = acc[nt*4+0] + acc[nt*4+2];
            s[nt*2+1] = acc[nt*4+1] + acc[nt*4+3];
            q[nt*2+0] = acc[nt*4+0]*acc[nt*4+0] + acc[nt*4+2]*acc[nt*4+2];
            q[nt*2+1] = acc[nt*4+1]*acc[nt*4+1] + acc[nt*4+3]*acc[nt*4+3];
        }
        #pragma unroll
        for (int off = 4; off < 32; off <<= 1) {
            #pragma unroll
            for (int u = 0; u < 8; ++u) {
                s[u] += __shfl_xor_sync(0xffffffffu, s[u], off);
                q[u] += __shfl_xor_sync(0xffffffffu, q[u], off);
            }
        }
        if (lane < 4) {
            #pragma unroll
            for (int nt = 0; nt < NTILES; ++nt) {
                int col = nt*8 + lane*2;
                red_s[col*16 + wid]     = s[nt*2+0];
                red_s[(col+1)*16 + wid] = s[nt*2+1];
                red_q[col*16 + wid]     = q[nt*2+0];
                red_q[(col+1)*16 + wid] = q[nt*2+1];
            }
        }
    }
    __syncthreads();
    if (tid < COLS_T) {
        float S = 0.0f, Q = 0.0f;
        #pragma unroll
        for (int mt = 0; mt < 16; ++mt) { S += red_s[tid*16+mt]; Q += red_q[tid*16+mt]; }
        float mu  = S * (1.0f/256.0f);
        float var = Q * (1.0f/256.0f) - mu*mu;
        smu[tid] = mu;
        srs[tid] = rsqrtf(var + 1e-5f);
    }
    __syncthreads();

    // ---- normalize in regs -> Ba fragments (buf0) ----
    #pragma unroll
    for (int nt = 0; nt < NTILES; ++nt) {
        int col = nt*8 + c2;
        float mA = smu[col],   rA = srs[col];
        float mB = smu[col+1], rB = srs[col+1];
        put3(buf0, m0+r,   col,   (acc[nt*4+0]-mA)*rA);
        put3(buf0, m0+r,   col+1, (acc[nt*4+1]-mB)*rB);
        put3(buf0, m0+r+8, col,   (acc[nt*4+2]-mA)*rA);
        put3(buf0, m0+r+8, col+1, (acc[nt*4+3]-mB)*rB);
    }
    __syncthreads();

    // ---- adapter conv1 (48 ks over buf0) + ReLU -> Bh (buf1) ----
    #pragma unroll
    for (int p = 0; p < 16; ++p) acc[p] = 0.0f;
    {
        const uint4* Aw = (const uint4*)g_Aa1 + ((size_t)wid*NKS_A*32 + lane);
        mma_span(acc, Aw, B0, 0, 48);
    }
    {
        float bb0 = __ldg(b_a1 + m0 + r);
        float bb1 = __ldg(b_a1 + m0 + r + 8);
        #pragma unroll
        for (int nt = 0; nt < NTILES; ++nt) {
            int col = nt*8 + c2;
            put3(buf1, m0+r,   col,   fmaxf(acc[nt*4+0]+bb0, 0.0f));
            put3(buf1, m0+r,   col+1, fmaxf(acc[nt*4+1]+bb0, 0.0f));
            put3(buf1, m0+r+8, col,   fmaxf(acc[nt*4+2]+bb1, 0.0f));
            put3(buf1, m0+r+8, col+1, fmaxf(acc[nt*4+3]+bb1, 0.0f));
        }
    }
    __syncthreads();

    // ---- adapter conv2 (48 ks over buf1) ----
    #pragma unroll
    for (int p = 0; p < 16; ++p) acc[p] = 0.0f;
    {
        const uint4* Aw = (const uint4*)g_Aa2 + ((size_t)wid*NKS_A*32 + lane);
        mma_span(acc, Aw, B1, 0, 48);
    }

    // ---- bias + output + loss ----
    float bb0 = __ldg(b_a2 + m0 + r);
    float bb1 = __ldg(b_a2 + m0 + r + 8);
    float ls = 0.0f;
    size_t ob0 = ((size_t)b * CH + (m0 + r)) * NSEED + ns0;
    size_t ob1 = ((size_t)b * CH + (m0 + r + 8)) * NSEED + ns0;
    bool full = (NFS <= out_size);
    #pragma unroll
    for (int nt = 0; nt < NTILES; ++nt) {
        int col = nt*8 + c2;
        float f0 = acc[nt*4+0]+bb0, f1 = acc[nt*4+1]+bb0;
        float f2 = acc[nt*4+2]+bb1, f3 = acc[nt*4+3]+bb1;
        if (full) {
            *(float2*)(out + ob0 + col) = make_float2(f0, f1);
            *(float2*)(out + ob1 + col) = make_float2(f2, f3);
        }
        float2 t0 = *(const float2*)(f_teacher + ob0 + col);
        float2 t1 = *(const float2*)(f_teacher + ob1 + col);
        float d0 = f0-t0.x, d1 = f1-t0.y, d2 = f2-t1.x, d3 = f3-t1.y;
        ls += d0*d0 + d1*d1 + d2*d2 + d3*d3;
    }
    #pragma unroll
    for (int o = 16; o; o >>= 1) ls += __shfl_xor_sync(0xffffffffu, ls, o);
    if (lane == 0) atomicAdd(&g_loss, ls);
}

// -------------------- kernel 3: finalize loss --------------------
__global__ void k_final(float* __restrict__ out, int out_size)
{
    float v = g_loss * (1.0f / (float)NFS);
    if (out_size > NFS) {
        for (int i = NFS + (int)threadIdx.x; i < out_size; i += (int)blockDim.x)
            out[i] = v;
    } else if (out_size > 0 && out_size < NFS && threadIdx.x == 0) {
        out[out_size - 1] = v;
    }
}

// -------------------- launch --------------------
extern "C" void kernel_launch(void* const* d_in, const int* in_sizes, int n_in,
                              void* d_out, int out_size)
{
    (void)in_sizes; (void)n_in;
    const float* seed_xyz    = (const float*)d_in[1];
    const float* pts         = (const float*)d_in[2];
    const float* feat        = (const float*)d_in[3];
    const float* f_teacher   = (const float*)d_in[4];
    const float* W_proj      = (const float*)d_in[5];
    const float* b_proj      = (const float*)d_in[6];
    const float* W_a1        = (const float*)d_in[7];
    const float* b_a1        = (const float*)d_in[8];
    const float* W_a2        = (const float*)d_in[9];
    const float* b_a2        = (const float*)d_in[10];
    float* out = (float*)d_out;

    cudaFuncSetAttribute(k_fused, cudaFuncAttributeMaxDynamicSharedMemorySize, SMEM_BYTES);

    k_zero<<<1, 1>>>();
    k_prep<<<(256*768 + 2*256*256 + 255)/256, 256>>>(W_proj, W_a1, W_a2);
    dim3 g1(BNS/128, 4);
    k_argmin<<<g1, 128>>>(seed_xyz, pts);
    k_fused<<<BNS/COLS_T, THREADS, SMEM_BYTES>>>(feat, f_teacher,
                                                 b_proj, b_a1, b_a2, out, out_size);
    k_final<<<1, 64>>>(out, out_size);
}

// round 6
// speedup vs baseline: 1.7178x; 1.0052x over previous
#include <cuda_runtime.h>
#include <cuda_bf16.h>
#include <cstdint>

#define BATCH 8
#define NSEED 2048
#define KPTS  16384
#define DIM   768
#define CH    256
#define BNS   (BATCH*NSEED)
#define NFS   (BATCH*CH*NSEED)
#define COLS_T 32
#define THREADS 512
#define NKS_P 144     // proj k-steps (K' = 2304)
#define NKS_A 48      // adapter k-steps (K' = 768)
#define NTILES 4
#define CHKS 48       // ksteps per proj chunk (= 256 dims)
#define CHDIM 256

typedef unsigned short ushort_t;

// -------------------- device scratch --------------------
__device__ float g_bestd[4*BNS];
__device__ int   g_besti[4*BNS];
__device__ float g_loss;
__device__ ushort_t g_Ap [16*NKS_P*32*4*2];
__device__ ushort_t g_Aa1[16*NKS_A*32*4*2];
__device__ ushort_t g_Aa2[16*NKS_A*32*4*2];

__global__ void k_zero() { g_loss = 0.0f; }

// -------------------- helpers --------------------
__device__ __forceinline__ void split_hilo(float x, ushort_t& h, ushort_t& l) {
    __nv_bfloat16 hb = __float2bfloat16(x);
    __nv_bfloat16 lb = __float2bfloat16(x - __bfloat162float(hb));
    h = __bfloat16_as_ushort(hb);
    l = __bfloat16_as_ushort(lb);
}
__device__ __forceinline__ unsigned long long pack2(float a, float b) {
    unsigned long long r;
    asm("mov.b64 %0, {%1, %2};" : "=l"(r) : "r"(__float_as_uint(a)), "r"(__float_as_uint(b)));
    return r;
}
__device__ __forceinline__ float2 unpack2(unsigned long long v) {
    unsigned int lo, hi;
    asm("mov.b64 {%0, %1}, %2;" : "=r"(lo), "=r"(hi) : "l"(v));
    return make_float2(__uint_as_float(lo), __uint_as_float(hi));
}
__device__ __forceinline__ unsigned long long fma2(unsigned long long a,
                                                   unsigned long long b,
                                                   unsigned long long c) {
    unsigned long long d;
    asm("fma.rn.f32x2 %0, %1, %2, %3;" : "=l"(d) : "l"(a), "l"(b), "l"(c));
    return d;
}

__device__ __forceinline__ size_t aidx_h(int o, int s, int nks) {
    int kstep = s >> 4, ks = s & 15;
    int mtile = o >> 4, mm = o & 15;
    int lane = (mm & 7) * 4 + ((ks >> 1) & 3);
    int word = ((mm >> 3) & 1) + 2 * ((ks >> 3) & 1);
    int half = ks & 1;
    return ((((size_t)mtile * nks + kstep) * 32 + lane) * 4 + word) * 2 + half;
}
__device__ __forceinline__ int bidx_h(int s, int n) {
    int kstep = s >> 4, ks = s & 15;
    int ntile = n >> 3;
    int lane = (n & 7) * 4 + ((ks >> 1) & 3);
    int wk = (ks >> 3) & 1;
    int half = ks & 1;
    return (((kstep * NTILES + ntile) * 32 + lane) * 2 + wk) * 2 + half;
}
__device__ __forceinline__ void put3(ushort_t* buf, int row, int col, float v) {
    ushort_t h, l; split_hilo(v, h, l);
    int s0 = 3*row;
    buf[bidx_h(s0,   col)] = h;
    buf[bidx_h(s0+1, col)] = l;
    buf[bidx_h(s0+2, col)] = h;
}
__device__ __forceinline__ void put_A(ushort_t* arr, int o, int d, int nks, float w) {
    ushort_t h, l; split_hilo(w, h, l);
    arr[aidx_h(o, 3*d+0, nks)] = h;
    arr[aidx_h(o, 3*d+1, nks)] = h;
    arr[aidx_h(o, 3*d+2, nks)] = l;
}

// -------------------- weight prep --------------------
__global__ __launch_bounds__(256) void k_prep(
    const float* __restrict__ Wp, const float* __restrict__ Wa1, const float* __restrict__ Wa2)
{
    int id = blockIdx.x * 256 + threadIdx.x;
    if (id < 256*768) {
        int o = id / 768, d = id % 768;
        put_A(g_Ap, o, d, NKS_P, Wp[id]);
    } else if (id < 256*768 + 256*256) {
        int t = id - 256*768; int o = t >> 8, d = t & 255;
        put_A(g_Aa1, o, d, NKS_A, Wa1[t]);
    } else if (id < 256*768 + 2*256*256) {
        int t = id - 256*768 - 256*256; int o = t >> 8, d = t & 255;
        put_A(g_Aa2, o, d, NKS_A, Wa2[t]);
    }
}

// -------------------- kernel 1: split-K argmin, f32x2 distances --------------------
__global__ __launch_bounds__(128) void k_argmin(
    const float* __restrict__ seed, const float* __restrict__ pts)
{
    __shared__ float4 tA[1024], tB[1024];   // pairs: (x0,x1,y0,y1), (z0,z1,w0,w1)
    int gs = blockIdx.x * 128 + threadIdx.x;
    int b  = gs >> 11;
    int kbase = blockIdx.y * 4096;
    const float* pb = pts + ((size_t)b * KPTS + kbase) * 3;

    float sx = seed[gs*3+0], sy = seed[gs*3+1], sz = seed[gs*3+2];
    unsigned long long mxx = pack2(-2.0f*sx, -2.0f*sx);
    unsigned long long myy = pack2(-2.0f*sy, -2.0f*sy);
    unsigned long long mzz = pack2(-2.0f*sz, -2.0f*sz);

    float bd = 1e30f;
    int   bi = kbase;

    for (int t0 = 0; t0 < 4096; t0 += 2048) {
        for (int p = threadIdx.x; p < 1024; p += 128) {
            const float* q = pb + (t0 + 2*p)*3;
            float x0=q[0], y0=q[1], z0=q[2], x1=q[3], y1=q[4], z1=q[5];
            tA[p] = make_float4(x0, x1, y0, y1);
            tB[p] = make_float4(z0, z1, x0*x0+y0*y0+z0*z0, x1*x1+y1*y1+z1*z1);
        }
        __syncthreads();
        #pragma unroll 8
        for (int p = 0; p < 1024; ++p) {
            float4 A = tA[p], B = tB[p];
            unsigned long long d2 =
                fma2(mxx, pack2(A.x, A.y),
                fma2(myy, pack2(A.z, A.w),
                fma2(mzz, pack2(B.x, B.y), pack2(B.z, B.w))));
            float2 d = unpack2(d2);
            if (d.x < bd) { bd = d.x; bi = kbase + t0 + 2*p; }
            if (d.y < bd) { bd = d.y; bi = kbase + t0 + 2*p + 1; }
        }
        __syncthreads();
    }
    g_bestd[blockIdx.y * BNS + gs] = bd;
    g_besti[blockIdx.y * BNS + gs] = bi;
}

// -------------------- mma helpers --------------------
__device__ __forceinline__ void mma16816(float* c, const uint4& a, const uint2& b) {
    asm volatile(
        "mma.sync.aligned.m16n8k16.row.col.f32.bf16.bf16.f32 "
        "{%0,%1,%2,%3}, {%4,%5,%6,%7}, {%8,%9}, {%0,%1,%2,%3};"
        : "+f"(c[0]), "+f"(c[1]), "+f"(c[2]), "+f"(c[3])
        : "r"(a.x), "r"(a.y), "r"(a.z), "r"(a.w), "r"(b.x), "r"(b.y));
}
__device__ __forceinline__ void mma_span(float acc[16],
    const uint4* __restrict__ Aw, const uint2* __restrict__ Bw, int ks0, int ks1)
{
    #pragma unroll 4
    for (int ks = ks0; ks < ks1; ++ks) {
        uint4 a = Aw[(size_t)ks*32];
        #pragma unroll
        for (int nt = 0; nt < NTILES; ++nt) {
            uint2 bw = Bw[(ks*NTILES + nt)*32];
            mma16816(acc + nt*4, a, bw);
        }
    }
}

// -------------------- smem layout --------------------
// buf0 [0, 49152), buf1 [49152, 98304)  -- 48-kstep fragment buffers
// red_s/red_q alias buf1 (dead window); smu/srs/idxs at tail
#define SMB_BUF1 49152
#define SMB_MU   98304
#define SMB_RS   98432
#define SMB_IDX  98560
#define SMEM_BYTES 98816

// -------------------- kernel 2: fused --------------------
__global__ void __launch_bounds__(THREADS, 2) k_fused(
    const float* __restrict__ feat, const float* __restrict__ f_teacher,
    const float* __restrict__ b_proj, const float* __restrict__ b_a1,
    const float* __restrict__ b_a2,
    float* __restrict__ out, int out_size)
{
    extern __shared__ char smraw[];
    ushort_t* buf0 = (ushort_t*)smraw;
    ushort_t* buf1 = (ushort_t*)(smraw + SMB_BUF1);
    float* red_s = (float*)(smraw + SMB_BUF1);          // alias buf1
    float* red_q = (float*)(smraw + SMB_BUF1 + 2048);
    float* smu   = (float*)(smraw + SMB_MU);
    float* srs   = (float*)(smraw + SMB_RS);
    int*   idxs  = (int*)(smraw + SMB_IDX);

    int tid  = threadIdx.x;
    int lane = tid & 31;
    int wid  = tid >> 5;
    int j0   = blockIdx.x * COLS_T;
    int b    = j0 >> 11;
    int ns0  = j0 & 2047;

    if (tid < COLS_T) {
        int gs = j0 + tid;
        float bd = g_bestd[gs];
        int   bi = g_besti[gs];
        #pragma unroll
        for (int y = 1; y < 4; ++y) {
            float d2 = g_bestd[y*BNS + gs];
            int   i2 = g_besti[y*BNS + gs];
            if (d2 < bd || (d2 == bd && i2 < bi)) { bd = d2; bi = i2; }
        }
        idxs[tid] = bi;
    }
    __syncthreads();

    // per-thread gather geometry: col is FIXED (= lane), dims stride 16
    const float* featb = feat + (size_t)b * DIM * KPTS;
    int mycol = tid & 31;
    int drow  = tid >> 5;                 // 0..15
    const float* gbase = featb + idxs[mycol];

    // ---- chunk 0 gather -> buf0 ----
    {
        float v[16];
        #pragma unroll
        for (int t = 0; t < 16; ++t)
            v[t] = __ldg(gbase + (size_t)(drow + t*16) * KPTS);
        #pragma unroll
        for (int t = 0; t < 16; ++t)
            put3(buf0, drow + t*16, mycol, v[t]);   // local row within chunk
    }
    __syncthreads();

    int r  = lane >> 2;
    int c2 = (lane & 3) * 2;
    int m0 = wid * 16;

    float acc[16];
    #pragma unroll
    for (int p = 0; p < 16; ++p) acc[p] = 0.0f;

    const uint4* Apw = (const uint4*)g_Ap + ((size_t)wid*NKS_P*32 + lane);
    const uint2* B0  = (const uint2*)buf0 + lane;
    const uint2* B1  = (const uint2*)buf1 + lane;

    // ---- projection: 3 chunks, pipelined gather ----
    #pragma unroll 1
    for (int c = 0; c < 3; ++c) {
        const uint2* Bw  = (c & 1) ? B1 : B0;
        ushort_t*    nbf = (c & 1) ? buf0 : buf1;
        const uint4* Aw  = Apw + (size_t)c*CHKS*32;
        bool more = (c < 2);
        int nb = (c+1)*CHDIM;
        float st[8];
        if (more) {
            #pragma unroll
            for (int t = 0; t < 8; ++t)
                st[t] = __ldg(gbase + (size_t)(nb + drow + t*16) * KPTS);
        }
        mma_span(acc, Aw, Bw, 0, 24);
        if (more) {
            #pragma unroll
            for (int t = 0; t < 8; ++t)
                put3(nbf, drow + t*16, mycol, st[t]);
            #pragma unroll
            for (int t = 0; t < 8; ++t)
                st[t] = __ldg(gbase + (size_t)(nb + drow + (8+t)*16) * KPTS);
        }
        mma_span(acc, Aw, Bw, 24, 48);
        if (more) {
            #pragma unroll
            for (int t = 0; t < 8; ++t)
                put3(nbf, drow + (8+t)*16, mycol, st[t]);
        }
        __syncthreads();
    }

    // ---- bias + LN stats in registers ----
    {
        float bb0 = __ldg(b_proj + m0 + r);
        float bb1 = __ldg(b_proj + m0 + r + 8);
        #pragma unroll
        for (int nt = 0; nt < NTILES; ++nt) {
            acc[nt*4+0] += bb0; acc[nt*4+1] += bb0;
            acc[nt*4+2] += bb1; acc[nt*4+3] += bb1;
        }
    }
    {
        float s[8], q[8];
        #pragma unroll
        for (int nt = 0; nt < NTILES; ++nt) {
            s[nt*2+0] = acc[nt*4+0] + acc[nt*4+2];
            s[nt*2+1] = acc[nt*4+1] + acc[nt*4+3];
            q[nt*2+0] = acc[nt*4+0]*acc[nt*4+0] + acc[nt*4+2]*acc[nt*4+2];
            q[nt*2+1] = acc[nt*4+1]*acc[nt*4+1] + acc[nt*4+3]*acc[nt*4+3];
        }
        #pragma unroll
        for (int off = 4; off < 32; off <<= 1) {
            #pragma unroll
            for (int u = 0; u < 8; ++u) {
                s[u] += __shfl_xor_sync(0xffffffffu, s[u], off);
                q[u] += __shfl_xor_sync(0xffffffffu, q[u], off);
            }
        }
        if (lane < 4) {
            #pragma unroll
            for (int nt = 0; nt < NTILES; ++nt) {
                int col = nt*8 + lane*2;
                red_s[col*16 + wid]     = s[nt*2+0];
                red_s[(col+1)*16 + wid] = s[nt*2+1];
                red_q[col*16 + wid]     = q[nt*2+0];
                red_q[(col+1)*16 + wid] = q[nt*2+1];
            }
        }
    }
    __syncthreads();
    if (tid < COLS_T) {
        float S = 0.0f, Q = 0.0f;
        #pragma unroll
        for (int mt = 0; mt < 16; ++mt) { S += red_s[tid*16+mt]; Q += red_q[tid*16+mt]; }
        float mu  = S * (1.0f/256.0f);
        float var = Q * (1.0f/256.0f) - mu*mu;
        smu[tid] = mu;
        srs[tid] = rsqrtf(var + 1e-5f);
    }
    __syncthreads();

    // ---- normalize in regs -> Ba fragments (buf0) ----
    #pragma unroll
    for (int nt = 0; nt < NTILES; ++nt) {
        int col = nt*8 + c2;
        float mA = smu[col],   rA = srs[col];
        float mB = smu[col+1], rB = srs[col+1];
        put3(buf0, m0+r,   col,   (acc[nt*4+0]-mA)*rA);
        put3(buf0, m0+r,   col+1, (acc[nt*4+1]-mB)*rB);
        put3(buf0, m0+r+8, col,   (acc[nt*4+2]-mA)*rA);
        put3(buf0, m0+r+8, col+1, (acc[nt*4+3]-mB)*rB);
    }
    __syncthreads();

    // ---- adapter conv1 (48 ks over buf0) + ReLU -> Bh (buf1) ----
    #pragma unroll
    for (int p = 0; p < 16; ++p) acc[p] = 0.0f;
    {
        const uint4* Aw = (const uint4*)g_Aa1 + ((size_t)wid*NKS_A*32 + lane);
        mma_span(acc, Aw, B0, 0, 48);
    }
    {
        float bb0 = __ldg(b_a1 + m0 + r);
        float bb1 = __ldg(b_a1 + m0 + r + 8);
        #pragma unroll
        for (int nt = 0; nt < NTILES; ++nt) {
            int col = nt*8 + c2;
            put3(buf1, m0+r,   col,   fmaxf(acc[nt*4+0]+bb0, 0.0f));
            put3(buf1, m0+r,   col+1, fmaxf(acc[nt*4+1]+bb0, 0.0f));
            put3(buf1, m0+r+8, col,   fmaxf(acc[nt*4+2]+bb1, 0.0f));
            put3(buf1, m0+r+8, col+1, fmaxf(acc[nt*4+3]+bb1, 0.0f));
        }
    }
    __syncthreads();

    // ---- adapter conv2 (48 ks over buf1) ----
    #pragma unroll
    for (int p = 0; p < 16; ++p) acc[p] = 0.0f;
    {
        const uint4* Aw = (const uint4*)g_Aa2 + ((size_t)wid*NKS_A*32 + lane);
        mma_span(acc, Aw, B1, 0, 48);
    }

    // ---- bias + output + loss ----
    float bb0 = __ldg(b_a2 + m0 + r);
    float bb1 = __ldg(b_a2 + m0 + r + 8);
    float ls = 0.0f;
    size_t ob0 = ((size_t)b * CH + (m0 + r)) * NSEED + ns0;
    size_t ob1 = ((size_t)b * CH + (m0 + r + 8)) * NSEED + ns0;
    bool full = (NFS <= out_size);
    #pragma unroll
    for (int nt = 0; nt < NTILES; ++nt) {
        int col = nt*8 + c2;
        float f0 = acc[nt*4+0]+bb0, f1 = acc[nt*4+1]+bb0;
        float f2 = acc[nt*4+2]+bb1, f3 = acc[nt*4+3]+bb1;
        if (full) {
            *(float2*)(out + ob0 + col) = make_float2(f0, f1);
            *(float2*)(out + ob1 + col) = make_float2(f2, f3);
        }
        float2 t0 = *(const float2*)(f_teacher + ob0 + col);
        float2 t1 = *(const float2*)(f_teacher + ob1 + col);
        float d0 = f0-t0.x, d1 = f1-t0.y, d2 = f2-t1.x, d3 = f3-t1.y;
        ls += d0*d0 + d1*d1 + d2*d2 + d3*d3;
    }
    #pragma unroll
    for (int o = 16; o; o >>= 1) ls += __shfl_xor_sync(0xffffffffu, ls, o);
    if (lane == 0) atomicAdd(&g_loss, ls);
}

// -------------------- kernel 3: finalize loss --------------------
__global__ void k_final(float* __restrict__ out, int out_size)
{
    float v = g_loss * (1.0f / (float)NFS);
    if (out_size > NFS) {
        for (int i = NFS + (int)threadIdx.x; i < out_size; i += (int)blockDim.x)
            out[i] = v;
    } else if (out_size > 0 && out_size < NFS && threadIdx.x == 0) {
        out[out_size - 1] = v;
    }
}

// -------------------- launch --------------------
extern "C" void kernel_launch(void* const* d_in, const int* in_sizes, int n_in,
                              void* d_out, int out_size)
{
    (void)in_sizes; (void)n_in;
    const float* seed_xyz    = (const float*)d_in[1];
    const float* pts         = (const float*)d_in[2];
    const float* feat        = (const float*)d_in[3];
    const float* f_teacher   = (const float*)d_in[4];
    const float* W_proj      = (const float*)d_in[5];
    const float* b_proj      = (const float*)d_in[6];
    const float* W_a1        = (const float*)d_in[7];
    const float* b_a1        = (const float*)d_in[8];
    const float* W_a2        = (const float*)d_in[9];
    const float* b_a2        = (const float*)d_in[10];
    float* out = (float*)d_out;

    cudaFuncSetAttribute(k_fused, cudaFuncAttributeMaxDynamicSharedMemorySize, SMEM_BYTES);

    k_zero<<<1, 1>>>();
    k_prep<<<(256*768 + 2*256*256 + 255)/256, 256>>>(W_proj, W_a1, W_a2);
    dim3 g1(BNS/128, 4);
    k_argmin<<<g1, 128>>>(seed_xyz, pts);
    k_fused<<<BNS/COLS_T, THREADS, SMEM_BYTES>>>(feat, f_teacher,
                                                 b_proj, b_a1, b_a2, out, out_size);
    k_final<<<1, 64>>>(out, out_size);
}

// round 7
// speedup vs baseline: 1.7471x; 1.0170x over previous
#include <cuda_runtime.h>
#include <cuda_bf16.h>
#include <cstdint>

#define BATCH 8
#define NSEED 2048
#define KPTS  16384
#define DIM   768
#define CH    256
#define BNS   (BATCH*NSEED)
#define NFS   (BATCH*CH*NSEED)
#define COLS_T 32
#define THREADS 512
#define NKS_P 144     // proj k-steps (K' = 2304)
#define NKS_A 48      // adapter k-steps (K' = 768)
#define NTILES 4
#define NSPLIT 8      // argmin split-K
#define CHKS 48       // ksteps per proj chunk (= 256 dims)
#define CHDIM 256

typedef unsigned short ushort_t;

// -------------------- device scratch --------------------
__device__ float g_bestd[NSPLIT*BNS];
__device__ int   g_besti[NSPLIT*BNS];
__device__ float g_loss;
__device__ ushort_t g_Ap [16*NKS_P*32*4*2];
__device__ ushort_t g_Aa1[16*NKS_A*32*4*2];
__device__ ushort_t g_Aa2[16*NKS_A*32*4*2];

__global__ void k_zero() { g_loss = 0.0f; }

// -------------------- helpers --------------------
__device__ __forceinline__ void split_hilo(float x, ushort_t& h, ushort_t& l) {
    __nv_bfloat16 hb = __float2bfloat16(x);
    __nv_bfloat16 lb = __float2bfloat16(x - __bfloat162float(hb));
    h = __bfloat16_as_ushort(hb);
    l = __bfloat16_as_ushort(lb);
}
__device__ __forceinline__ unsigned long long pack2(float a, float b) {
    unsigned long long r;
    asm("mov.b64 %0, {%1, %2};" : "=l"(r) : "r"(__float_as_uint(a)), "r"(__float_as_uint(b)));
    return r;
}
__device__ __forceinline__ float2 unpack2(unsigned long long v) {
    unsigned int lo, hi;
    asm("mov.b64 {%0, %1}, %2;" : "=r"(lo), "=r"(hi) : "l"(v));
    return make_float2(__uint_as_float(lo), __uint_as_float(hi));
}
__device__ __forceinline__ unsigned long long fma2(unsigned long long a,
                                                   unsigned long long b,
                                                   unsigned long long c) {
    unsigned long long d;
    asm("fma.rn.f32x2 %0, %1, %2, %3;" : "=l"(d) : "l"(a), "l"(b), "l"(c));
    return d;
}

// A halfword index (unchanged layout)
__device__ __forceinline__ size_t aidx_h(int o, int s, int nks) {
    int kstep = s >> 4, ks = s & 15;
    int mtile = o >> 4, mm = o & 15;
    int lane = (mm & 7) * 4 + ((ks >> 1) & 3);
    int word = ((mm >> 3) & 1) + 2 * ((ks >> 3) & 1);
    int half = ks & 1;
    return ((((size_t)mtile * nks + kstep) * 32 + lane) * 4 + word) * 2 + half;
}
// B halfword index, NEW: uint4-per-(kstep, ntile-pair) layout
__device__ __forceinline__ int bidx_h(int s, int n) {
    int kstep = s >> 4, ks = s & 15;
    int nt = n >> 3, np = nt >> 1, ntip = nt & 1;
    int lane = (n & 7) * 4 + ((ks >> 1) & 3);
    int wk = (ks >> 3) & 1;
    int half = ks & 1;
    return (((kstep * 2 + np) * 32 + lane) * 4 + (ntip * 2 + wk)) * 2 + half;
}
// 2-store put3: slots 3r..3r+2 = (h,l,h); adjacent even/odd slots share a 32-bit word
__device__ __forceinline__ void put3(ushort_t* buf, int row, int col, float v) {
    ushort_t h, l; split_hilo(v, h, l);
    int s0 = 3 * row;
    if ((row & 1) == 0) {
        int wi = bidx_h(s0, col) >> 1;              // word holding (s0, s0+1)
        *((unsigned*)buf + wi) = (unsigned)h | ((unsigned)l << 16);
        buf[bidx_h(s0 + 2, col)] = h;
    } else {
        buf[bidx_h(s0, col)] = h;
        int wi = bidx_h(s0 + 1, col) >> 1;          // word holding (s0+1, s0+2)
        *((unsigned*)buf + wi) = (unsigned)l | ((unsigned)h << 16);
    }
}
__device__ __forceinline__ void put_A(ushort_t* arr, int o, int d, int nks, float w) {
    ushort_t h, l; split_hilo(w, h, l);
    arr[aidx_h(o, 3*d+0, nks)] = h;
    arr[aidx_h(o, 3*d+1, nks)] = h;
    arr[aidx_h(o, 3*d+2, nks)] = l;
}

// -------------------- weight prep --------------------
__global__ __launch_bounds__(256) void k_prep(
    const float* __restrict__ Wp, const float* __restrict__ Wa1, const float* __restrict__ Wa2)
{
    int id = blockIdx.x * 256 + threadIdx.x;
    if (id < 256*768) {
        int o = id / 768, d = id % 768;
        put_A(g_Ap, o, d, NKS_P, Wp[id]);
    } else if (id < 256*768 + 256*256) {
        int t = id - 256*768; int o = t >> 8, d = t & 255;
        put_A(g_Aa1, o, d, NKS_A, Wa1[t]);
    } else if (id < 256*768 + 2*256*256) {
        int t = id - 256*768 - 256*256; int o = t >> 8, d = t & 255;
        put_A(g_Aa2, o, d, NKS_A, Wa2[t]);
    }
}

// -------------------- kernel 1: split-K argmin (8-way) --------------------
__global__ __launch_bounds__(128) void k_argmin(
    const float* __restrict__ seed, const float* __restrict__ pts)
{
    __shared__ float4 tA[1024], tB[1024];
    int gs = blockIdx.x * 128 + threadIdx.x;
    int b  = gs >> 11;
    int kbase = blockIdx.y * 2048;
    const float* pb = pts + ((size_t)b * KPTS + kbase) * 3;

    float sx = seed[gs*3+0], sy = seed[gs*3+1], sz = seed[gs*3+2];
    unsigned long long mxx = pack2(-2.0f*sx, -2.0f*sx);
    unsigned long long myy = pack2(-2.0f*sy, -2.0f*sy);
    unsigned long long mzz = pack2(-2.0f*sz, -2.0f*sz);

    float bd = 1e30f;
    int   bi = kbase;

    for (int p = threadIdx.x; p < 1024; p += 128) {
        const float* q = pb + 6*p;
        float x0=q[0], y0=q[1], z0=q[2], x1=q[3], y1=q[4], z1=q[5];
        tA[p] = make_float4(x0, x1, y0, y1);
        tB[p] = make_float4(z0, z1, x0*x0+y0*y0+z0*z0, x1*x1+y1*y1+z1*z1);
    }
    __syncthreads();
    #pragma unroll 8
    for (int p = 0; p < 1024; ++p) {
        float4 A = tA[p], B = tB[p];
        unsigned long long d2 =
            fma2(mxx, pack2(A.x, A.y),
            fma2(myy, pack2(A.z, A.w),
            fma2(mzz, pack2(B.x, B.y), pack2(B.z, B.w))));
        float2 d = unpack2(d2);
        if (d.x < bd) { bd = d.x; bi = kbase + 2*p; }
        if (d.y < bd) { bd = d.y; bi = kbase + 2*p + 1; }
    }
    g_bestd[blockIdx.y * BNS + gs] = bd;
    g_besti[blockIdx.y * BNS + gs] = bi;
}

// -------------------- mma helpers --------------------
__device__ __forceinline__ void mma16816(float* c, const uint4& a, unsigned b0, unsigned b1) {
    asm volatile(
        "mma.sync.aligned.m16n8k16.row.col.f32.bf16.bf16.f32 "
        "{%0,%1,%2,%3}, {%4,%5,%6,%7}, {%8,%9}, {%0,%1,%2,%3};"
        : "+f"(c[0]), "+f"(c[1]), "+f"(c[2]), "+f"(c[3])
        : "r"(a.x), "r"(a.y), "r"(a.z), "r"(a.w), "r"(b0), "r"(b1));
}
// Bw: uint4 base (+lane); per kstep: 2 x LDS.128 feeding 4 MMAs
__device__ __forceinline__ void mma_span(float acc[16],
    const uint4* __restrict__ Aw, const uint4* __restrict__ Bw, int ks0, int ks1)
{
    #pragma unroll 4
    for (int ks = ks0; ks < ks1; ++ks) {
        uint4 a  = Aw[(size_t)ks*32];
        uint4 b0 = Bw[(ks*2+0)*32];
        mma16816(acc + 0,  a, b0.x, b0.y);
        mma16816(acc + 4,  a, b0.z, b0.w);
        uint4 b1 = Bw[(ks*2+1)*32];
        mma16816(acc + 8,  a, b1.x, b1.y);
        mma16816(acc + 12, a, b1.z, b1.w);
    }
}

// -------------------- smem layout --------------------
#define SMB_BUF1 49152
#define SMB_MU   98304
#define SMB_RS   98432
#define SMB_IDX  98560
#define SMEM_BYTES 98816

// -------------------- kernel 2: fused --------------------
__global__ void __launch_bounds__(THREADS, 2) k_fused(
    const float* __restrict__ feat, const float* __restrict__ f_teacher,
    const float* __restrict__ b_proj, const float* __restrict__ b_a1,
    const float* __restrict__ b_a2,
    float* __restrict__ out, int out_size)
{
    extern __shared__ char smraw[];
    ushort_t* buf0 = (ushort_t*)smraw;
    ushort_t* buf1 = (ushort_t*)(smraw + SMB_BUF1);
    float* red_s = (float*)(smraw + SMB_BUF1);          // alias buf1
    float* red_q = (float*)(smraw + SMB_BUF1 + 2048);
    float* smu   = (float*)(smraw + SMB_MU);
    float* srs   = (float*)(smraw + SMB_RS);
    int*   idxs  = (int*)(smraw + SMB_IDX);

    int tid  = threadIdx.x;
    int lane = tid & 31;
    int wid  = tid >> 5;
    int j0   = blockIdx.x * COLS_T;
    int b    = j0 >> 11;
    int ns0  = j0 & 2047;

    if (tid < COLS_T) {
        int gs = j0 + tid;
        float bd = g_bestd[gs];
        int   bi = g_besti[gs];
        #pragma unroll
        for (int y = 1; y < NSPLIT; ++y) {
            float d2 = g_bestd[y*BNS + gs];
            int   i2 = g_besti[y*BNS + gs];
            if (d2 < bd || (d2 == bd && i2 < bi)) { bd = d2; bi = i2; }
        }
        idxs[tid] = bi;
    }
    __syncthreads();

    const float* featb = feat + (size_t)b * DIM * KPTS;
    int mycol = tid & 31;
    int drow  = tid >> 5;
    const float* gbase = featb + idxs[mycol];

    // ---- chunk 0 gather -> buf0 ----
    {
        float v[16];
        #pragma unroll
        for (int t = 0; t < 16; ++t)
            v[t] = __ldg(gbase + (size_t)(drow + t*16) * KPTS);
        #pragma unroll
        for (int t = 0; t < 16; ++t)
            put3(buf0, drow + t*16, mycol, v[t]);
    }
    __syncthreads();

    int r  = lane >> 2;
    int c2 = (lane & 3) * 2;
    int m0 = wid * 16;

    float acc[16];
    #pragma unroll
    for (int p = 0; p < 16; ++p) acc[p] = 0.0f;

    const uint4* Apw = (const uint4*)g_Ap + ((size_t)wid*NKS_P*32 + lane);
    const uint4* B0  = (const uint4*)buf0 + lane;
    const uint4* B1  = (const uint4*)buf1 + lane;

    // ---- projection: 3 chunks, pipelined gather ----
    #pragma unroll 1
    for (int c = 0; c < 3; ++c) {
        const uint4* Bw  = (c & 1) ? B1 : B0;
        ushort_t*    nbf = (c & 1) ? buf0 : buf1;
        const uint4* Aw  = Apw + (size_t)c*CHKS*32;
        bool more = (c < 2);
        int nb = (c+1)*CHDIM;
        float st[8];
        if (more) {
            #pragma unroll
            for (int t = 0; t < 8; ++t)
                st[t] = __ldg(gbase + (size_t)(nb + drow + t*16) * KPTS);
        }
        mma_span(acc, Aw, Bw, 0, 24);
        if (more) {
            #pragma unroll
            for (int t = 0; t < 8; ++t)
                put3(nbf, drow + t*16, mycol, st[t]);
            #pragma unroll
            for (int t = 0; t < 8; ++t)
                st[t] = __ldg(gbase + (size_t)(nb + drow + (8+t)*16) * KPTS);
        }
        mma_span(acc, Aw, Bw, 24, 48);
        if (more) {
            #pragma unroll
            for (int t = 0; t < 8; ++t)
                put3(nbf, drow + (8+t)*16, mycol, st[t]);
        }
        __syncthreads();
    }

    // ---- bias + LN stats ----
    {
        float bb0 = __ldg(b_proj + m0 + r);
        float bb1 = __ldg(b_proj + m0 + r + 8);
        #pragma unroll
        for (int nt = 0; nt < NTILES; ++nt) {
            acc[nt*4+0] += bb0; acc[nt*4+1] += bb0;
            acc[nt*4+2] += bb1; acc[nt*4+3] += bb1;
        }
    }
    {
        float s[8], q[8];
        #pragma unroll
        for (int nt = 0; nt < NTILES; ++nt) {
            s[nt*2+0] = acc[nt*4+0] + acc[nt*4+2];
            s[nt*2+1] = acc[nt*4+1] + acc[nt*4+3];
            q[nt*2+0] = acc[nt*4+0]*acc[nt*4+0] + acc[nt*4+2]*acc[nt*4+2];
            q[nt*2+1] = acc[nt*4+1]*acc[nt*4+1] + acc[nt*4+3]*acc[nt*4+3];
        }
        #pragma unroll
        for (int off = 4; off < 32; off <<= 1) {
            #pragma unroll
            for (int u = 0; u < 8; ++u) {
                s[u] += __shfl_xor_sync(0xffffffffu, s[u], off);
                q[u] += __shfl_xor_sync(0xffffffffu, q[u], off);
            }
        }
        if (lane < 4) {
            #pragma unroll
            for (int nt = 0; nt < NTILES; ++nt) {
                int col = nt*8 + lane*2;
                red_s[col*16 + wid]     = s[nt*2+0];
                red_s[(col+1)*16 + wid] = s[nt*2+1];
                red_q[col*16 + wid]     = q[nt*2+0];
                red_q[(col+1)*16 + wid] = q[nt*2+1];
            }
        }
    }
    __syncthreads();
    if (tid < COLS_T) {
        float S = 0.0f, Q = 0.0f;
        #pragma unroll
        for (int mt = 0; mt < 16; ++mt) { S += red_s[tid*16+mt]; Q += red_q[tid*16+mt]; }
        float mu  = S * (1.0f/256.0f);
        float var = Q * (1.0f/256.0f) - mu*mu;
        smu[tid] = mu;
        srs[tid] = rsqrtf(var + 1e-5f);
    }
    __syncthreads();

    // ---- normalize -> Ba (buf0) ----
    #pragma unroll
    for (int nt = 0; nt < NTILES; ++nt) {
        int col = nt*8 + c2;
        float mA = smu[col],   rA = srs[col];
        float mB = smu[col+1], rB = srs[col+1];
        put3(buf0, m0+r,   col,   (acc[nt*4+0]-mA)*rA);
        put3(buf0, m0+r,   col+1, (acc[nt*4+1]-mB)*rB);
        put3(buf0, m0+r+8, col,   (acc[nt*4+2]-mA)*rA);
        put3(buf0, m0+r+8, col+1, (acc[nt*4+3]-mB)*rB);
    }
    __syncthreads();

    // ---- adapter conv1 + ReLU -> buf1 ----
    #pragma unroll
    for (int p = 0; p < 16; ++p) acc[p] = 0.0f;
    {
        const uint4* Aw = (const uint4*)g_Aa1 + ((size_t)wid*NKS_A*32 + lane);
        mma_span(acc, Aw, B0, 0, 48);
    }
    {
        float bb0 = __ldg(b_a1 + m0 + r);
        float bb1 = __ldg(b_a1 + m0 + r + 8);
        #pragma unroll
        for (int nt = 0; nt < NTILES; ++nt) {
            int col = nt*8 + c2;
            put3(buf1, m0+r,   col,   fmaxf(acc[nt*4+0]+bb0, 0.0f));
            put3(buf1, m0+r,   col+1, fmaxf(acc[nt*4+1]+bb0, 0.0f));
            put3(buf1, m0+r+8, col,   fmaxf(acc[nt*4+2]+bb1, 0.0f));
            put3(buf1, m0+r+8, col+1, fmaxf(acc[nt*4+3]+bb1, 0.0f));
        }
    }
    __syncthreads();

    // ---- adapter conv2 ----
    #pragma unroll
    for (int p = 0; p < 16; ++p) acc[p] = 0.0f;
    {
        const uint4* Aw = (const uint4*)g_Aa2 + ((size_t)wid*NKS_A*32 + lane);
        mma_span(acc, Aw, B1, 0, 48);
    }

    // ---- bias + output + loss ----
    float bb0 = __ldg(b_a2 + m0 + r);
    float bb1 = __ldg(b_a2 + m0 + r + 8);
    float ls = 0.0f;
    size_t ob0 = ((size_t)b * CH + (m0 + r)) * NSEED + ns0;
    size_t ob1 = ((size_t)b * CH + (m0 + r + 8)) * NSEED + ns0;
    bool full = (NFS <= out_size);
    #pragma unroll
    for (int nt = 0; nt < NTILES; ++nt) {
        int col = nt*8 + c2;
        float f0 = acc[nt*4+0]+bb0, f1 = acc[nt*4+1]+bb0;
        float f2 = acc[nt*4+2]+bb1, f3 = acc[nt*4+3]+bb1;
        if (full) {
            *(float2*)(out + ob0 + col) = make_float2(f0, f1);
            *(float2*)(out + ob1 + col) = make_float2(f2, f3);
        }
        float2 t0 = *(const float2*)(f_teacher + ob0 + col);
        float2 t1 = *(const float2*)(f_teacher + ob1 + col);
        float d0 = f0-t0.x, d1 = f1-t0.y, d2 = f2-t1.x, d3 = f3-t1.y;
        ls += d0*d0 + d1*d1 + d2*d2 + d3*d3;
    }
    #pragma unroll
    for (int o = 16; o; o >>= 1) ls += __shfl_xor_sync(0xffffffffu, ls, o);
    if (lane == 0) atomicAdd(&g_loss, ls);
}

// -------------------- kernel 3: finalize loss --------------------
__global__ void k_final(float* __restrict__ out, int out_size)
{
    float v = g_loss * (1.0f / (float)NFS);
    if (out_size > NFS) {
        for (int i = NFS + (int)threadIdx.x; i < out_size; i += (int)blockDim.x)
            out[i] = v;
    } else if (out_size > 0 && out_size < NFS && threadIdx.x == 0) {
        out[out_size - 1] = v;
    }
}

// -------------------- launch --------------------
extern "C" void kernel_launch(void* const* d_in, const int* in_sizes, int n_in,
                              void* d_out, int out_size)
{
    (void)in_sizes; (void)n_in;
    const float* seed_xyz    = (const float*)d_in[1];
    const float* pts         = (const float*)d_in[2];
    const float* feat        = (const float*)d_in[3];
    const float* f_teacher   = (const float*)d_in[4];
    const float* W_proj      = (const float*)d_in[5];
    const float* b_proj      = (const float*)d_in[6];
    const float* W_a1        = (const float*)d_in[7];
    const float* b_a1        = (const float*)d_in[8];
    const float* W_a2        = (const float*)d_in[9];
    const float* b_a2        = (const float*)d_in[10];
    float* out = (float*)d_out;

    cudaFuncSetAttribute(k_fused, cudaFuncAttributeMaxDynamicSharedMemorySize, SMEM_BYTES);

    k_zero<<<1, 1>>>();
    k_prep<<<(256*768 + 2*256*256 + 255)/256, 256>>>(W_proj, W_a1, W_a2);
    dim3 g1(BNS/128, NSPLIT);
    k_argmin<<<g1, 128>>>(seed_xyz, pts);
    k_fused<<<BNS/COLS_T, THREADS, SMEM_BYTES>>>(feat, f_teacher,
                                                 b_proj, b_a1, b_a2, out, out_size);
    k_final<<<1, 64>>>(out, out_size);
}